// round 6
// baseline (speedup 1.0000x reference)
#include <cuda_runtime.h>
#include <cuda_bf16.h>
#include <cstdint>

// ---------------------------------------------------------------------------
// TransformerBlock B=8,T=1024,E=1024,H=16,HD=64,HID=4096 fp32.
// R5: occupancy fix. GEMM = 128x128x32 CTA tile, 128 threads (4 warps x
// 64x64), 2-stage cp.async -> 2 CTAs/SM. Flash attention single-buffered
// K/V (103KB smem) -> 2 CTAs/SM.
// ---------------------------------------------------------------------------

#define RROWS 8192
#define EDIM  1024
#define HEADS 16
#define HD    64
#define HID   4096
#define TSEQ  1024
#define BATCH 8

__device__ float g_xn  [RROWS * EDIM];
__device__ float g_qkv [RROWS * 3 * EDIM];
__device__ float g_ycat[RROWS * EDIM];
__device__ float g_h   [RROWS * HID];

__device__ __forceinline__ float gelu_tanh(float x) {
    float x3 = x * x * x;
    return 0.5f * x * (1.0f + tanhf(0.7978845608028654f * (x + 0.044715f * x3)));
}
__device__ __forceinline__ uint32_t f2tf32(float x) {
    uint32_t r;
    asm("cvt.rna.tf32.f32 %0, %1;" : "=r"(r) : "f"(x));
    return r;
}
__device__ __forceinline__ void cp_async16(void* smem_dst, const void* gsrc) {
    uint32_t d = (uint32_t)__cvta_generic_to_shared(smem_dst);
    asm volatile("cp.async.cg.shared.global [%0], [%1], 16;\n" :: "r"(d), "l"(gsrc));
}
__device__ __forceinline__ void cp_commit() { asm volatile("cp.async.commit_group;\n"); }
template <int N>
__device__ __forceinline__ void cp_wait() { asm volatile("cp.async.wait_group %0;\n" :: "n"(N)); }

__device__ __forceinline__ void mma_tf32(float* c, const uint32_t* a, const uint32_t* b) {
    asm volatile(
        "mma.sync.aligned.m16n8k8.row.col.f32.tf32.tf32.f32 "
        "{%0,%1,%2,%3}, {%4,%5,%6,%7}, {%8,%9}, {%0,%1,%2,%3};"
        : "+f"(c[0]), "+f"(c[1]), "+f"(c[2]), "+f"(c[3])
        : "r"(a[0]), "r"(a[1]), "r"(a[2]), "r"(a[3]), "r"(b[0]), "r"(b[1]));
}

// ---------------------------------------------------------------------------
// LayerNorm: one block (256 threads) per 1024-col row.
// ---------------------------------------------------------------------------
__global__ void ln_kernel(const float* __restrict__ x,
                          const float* __restrict__ g,
                          const float* __restrict__ b,
                          float* __restrict__ out) {
    __shared__ float red[8];
    const long long row = blockIdx.x;
    const int t = threadIdx.x;
    float4 v = ((const float4*)(x + row * EDIM))[t];

    float s = v.x + v.y + v.z + v.w;
    #pragma unroll
    for (int o = 16; o; o >>= 1) s += __shfl_xor_sync(~0u, s, o);
    if ((t & 31) == 0) red[t >> 5] = s;
    __syncthreads();
    if (t < 8) {
        s = red[t];
        #pragma unroll
        for (int o = 4; o; o >>= 1) s += __shfl_xor_sync(0xffu, s, o);
        if (t == 0) red[0] = s;
    }
    __syncthreads();
    const float mean = red[0] * (1.0f / EDIM);

    float dx = v.x - mean, dy = v.y - mean, dz = v.z - mean, dw = v.w - mean;
    float q = dx * dx + dy * dy + dz * dz + dw * dw;
    #pragma unroll
    for (int o = 16; o; o >>= 1) q += __shfl_xor_sync(~0u, q, o);
    __syncthreads();
    if ((t & 31) == 0) red[t >> 5] = q;
    __syncthreads();
    if (t < 8) {
        q = red[t];
        #pragma unroll
        for (int o = 4; o; o >>= 1) q += __shfl_xor_sync(0xffu, q, o);
        if (t == 0) red[0] = q;
    }
    __syncthreads();
    const float rstd = rsqrtf(red[0] * (1.0f / EDIM) + 1e-5f);

    const float4 gg = ((const float4*)g)[t];
    const float4 bb = ((const float4*)b)[t];
    float4 o4;
    o4.x = dx * rstd * gg.x + bb.x;
    o4.y = dy * rstd * gg.y + bb.y;
    o4.z = dz * rstd * gg.z + bb.z;
    o4.w = dw * rstd * gg.w + bb.w;
    ((float4*)(out + row * EDIM))[t] = o4;
}

// ---------------------------------------------------------------------------
// Flash attention, non-causal. CTA = 128 q-rows of one (b,h); 4 warps.
// Single-buffered K/V tiles of 64 keys (103KB smem -> 2 CTAs/SM).
// ---------------------------------------------------------------------------
#define KSTR 68
#define VSTR 72
#define FL_QOFF 0
#define FL_KOFF (128 * KSTR)
#define FL_VOFF (FL_KOFF + 64 * KSTR)
#define FL_POFF (FL_VOFF + 64 * VSTR)
#define FL_SMEM_F (FL_POFF + 128 * KSTR)

__global__ void __launch_bounds__(128)
flash_kernel(const float* __restrict__ qkv, float* __restrict__ ycat) {
    extern __shared__ float sm[];
    float* Qsm = sm + FL_QOFF;
    float* Ks  = sm + FL_KOFF;
    float* Vs  = sm + FL_VOFF;
    float* Psm = sm + FL_POFF;

    const int tid  = threadIdx.x;
    const int lane = tid & 31;
    const int warp = tid >> 5;
    const int lr = lane >> 2;
    const int lc = lane & 3;
    const int q0 = blockIdx.x * 128;
    const int h  = blockIdx.y;
    const int b  = blockIdx.z;
    const int wm = warp * 32;

    const float* qkvb = qkv + (long long)b * TSEQ * 3 * EDIM;
    const float* Qg = qkvb + h * HD;
    const float* Kg = qkvb + EDIM + h * HD;
    const float* Vg = qkvb + 2 * EDIM + h * HD;

    #pragma unroll
    for (int i = tid; i < 128 * 16; i += 128) {
        int r = i >> 4, c4 = (i & 15) << 2;
        float4 v = *(const float4*)(Qg + (long long)(q0 + r) * 3 * EDIM + c4);
        float* d = Qsm + r * KSTR + c4;
        d[0] = v.x * 0.125f; d[1] = v.y * 0.125f; d[2] = v.z * 0.125f; d[3] = v.w * 0.125f;
    }

    float o[2][8][4];
    float m[2][2], l[2][2];
    #pragma unroll
    for (int im = 0; im < 2; im++) {
        #pragma unroll
        for (int jn = 0; jn < 8; jn++)
            #pragma unroll
            for (int q = 0; q < 4; q++) o[im][jn][q] = 0.0f;
        m[im][0] = m[im][1] = -1e30f;
        l[im][0] = l[im][1] = 0.0f;
    }

    const int NT = TSEQ / 64;
    for (int j = 0; j < NT; j++) {
        __syncthreads();   // prior iter's PV reads of Vs done before overwrite
        {
            const float* Kj = Kg + (long long)(j * 64) * 3 * EDIM;
            const float* Vj = Vg + (long long)(j * 64) * 3 * EDIM;
            #pragma unroll
            for (int i = tid; i < 64 * 16; i += 128) {
                int r = i >> 4, c4 = (i & 15) << 2;
                cp_async16(Ks + r * KSTR + c4, Kj + (long long)r * 3 * EDIM + c4);
                cp_async16(Vs + r * VSTR + c4, Vj + (long long)r * 3 * EDIM + c4);
            }
            cp_commit();
        }
        cp_wait<0>();
        __syncthreads();

        // ---- S = Q K^T ----
        float s[2][8][4];
        #pragma unroll
        for (int im = 0; im < 2; im++)
            #pragma unroll
            for (int jn = 0; jn < 8; jn++)
                #pragma unroll
                for (int q = 0; q < 4; q++) s[im][jn][q] = 0.0f;

        #pragma unroll
        for (int kq = 0; kq < HD; kq += 8) {
            uint32_t afr[2][4];
            #pragma unroll
            for (int im = 0; im < 2; im++) {
                const float* Ab = Qsm + (wm + im * 16 + lr) * KSTR + kq + lc;
                afr[im][0] = f2tf32(Ab[0]);
                afr[im][1] = f2tf32(Ab[8 * KSTR]);
                afr[im][2] = f2tf32(Ab[4]);
                afr[im][3] = f2tf32(Ab[8 * KSTR + 4]);
            }
            #pragma unroll
            for (int jn = 0; jn < 8; jn++) {
                const float* Bb = Ks + (jn * 8 + lr) * KSTR + kq + lc;
                uint32_t bfr[2];
                bfr[0] = f2tf32(Bb[0]);
                bfr[1] = f2tf32(Bb[4]);
                #pragma unroll
                for (int im = 0; im < 2; im++) mma_tf32(s[im][jn], afr[im], bfr);
            }
        }

        // ---- online softmax; write P (own rows) ----
        #pragma unroll
        for (int im = 0; im < 2; im++) {
            #pragma unroll
            for (int hf = 0; hf < 2; hf++) {
                float mx = -1e30f;
                #pragma unroll
                for (int jn = 0; jn < 8; jn++)
                    mx = fmaxf(mx, fmaxf(s[im][jn][hf * 2], s[im][jn][hf * 2 + 1]));
                mx = fmaxf(mx, __shfl_xor_sync(~0u, mx, 1));
                mx = fmaxf(mx, __shfl_xor_sync(~0u, mx, 2));
                const float mnew = fmaxf(m[im][hf], mx);
                const float alpha = __expf(m[im][hf] - mnew);
                m[im][hf] = mnew;
                const int prow = wm + im * 16 + hf * 8 + lr;
                float sum = 0.0f;
                #pragma unroll
                for (int jn = 0; jn < 8; jn++) {
                    float p0 = __expf(s[im][jn][hf * 2]     - mnew);
                    float p1 = __expf(s[im][jn][hf * 2 + 1] - mnew);
                    sum += p0 + p1;
                    *(float2*)(Psm + prow * KSTR + jn * 8 + 2 * lc) = make_float2(p0, p1);
                }
                sum += __shfl_xor_sync(~0u, sum, 1);
                sum += __shfl_xor_sync(~0u, sum, 2);
                l[im][hf] = l[im][hf] * alpha + sum;
                #pragma unroll
                for (int jn = 0; jn < 8; jn++) {
                    o[im][jn][hf * 2]     *= alpha;
                    o[im][jn][hf * 2 + 1] *= alpha;
                }
            }
        }
        __syncwarp();

        // ---- O += P @ V ----
        #pragma unroll
        for (int kq = 0; kq < 64; kq += 8) {
            uint32_t afr[2][4];
            #pragma unroll
            for (int im = 0; im < 2; im++) {
                const float* Ab = Psm + (wm + im * 16 + lr) * KSTR + kq + lc;
                afr[im][0] = f2tf32(Ab[0]);
                afr[im][1] = f2tf32(Ab[8 * KSTR]);
                afr[im][2] = f2tf32(Ab[4]);
                afr[im][3] = f2tf32(Ab[8 * KSTR + 4]);
            }
            #pragma unroll
            for (int jn = 0; jn < 8; jn++) {
                const float* Bb = Vs + (kq + lc) * VSTR + jn * 8 + lr;
                uint32_t bfr[2];
                bfr[0] = f2tf32(Bb[0]);
                bfr[1] = f2tf32(Bb[4 * VSTR]);
                #pragma unroll
                for (int im = 0; im < 2; im++) mma_tf32(o[im][jn], afr[im], bfr);
            }
        }
    }

    #pragma unroll
    for (int im = 0; im < 2; im++) {
        #pragma unroll
        for (int hf = 0; hf < 2; hf++) {
            const float inv = 1.0f / l[im][hf];
            const long long row = (long long)b * TSEQ + q0 + wm + im * 16 + hf * 8 + lr;
            #pragma unroll
            for (int jn = 0; jn < 8; jn++) {
                *(float2*)(ycat + row * EDIM + h * HD + jn * 8 + 2 * lc) =
                    make_float2(o[im][jn][hf * 2] * inv, o[im][jn][hf * 2 + 1] * inv);
            }
        }
    }
}

// ---------------------------------------------------------------------------
// TF32 GEMM: 128x128x32 CTA tile, 128 threads = 4 warps x (64x64),
// 2-stage cp.async. 254 regs x 128 thr -> 2 CTAs/SM.
//   EPI: 1 +bias, 2 +bias,GELU, 3 +bias,+res (stride ldc).
// ---------------------------------------------------------------------------
#define GBM 128
#define GBN 128
#define GBK 32
#define ASTR 36     // GBK+4
#define BSTR 136    // GBN+8
#define AS_F (GBM * ASTR)
#define BS_F (GBK * BSTR)
#define G_SMEM_F (2 * (AS_F + BS_F))

template <int EPI>
__global__ void __launch_bounds__(128)
mma_gemm(int K,
         const float* __restrict__ A, int lda,
         const float* __restrict__ B, int ldb,
         float* __restrict__ C, int ldc,
         const float* __restrict__ bias,
         const float* __restrict__ res) {
    extern __shared__ float sm[];
    const int m0 = blockIdx.y * GBM;
    const int n0 = blockIdx.x * GBN;
    const int tid  = threadIdx.x;
    const int lane = tid & 31;
    const int warp = tid >> 5;
    const int wm = (warp >> 1) * 64;
    const int wn = (warp & 1) * 64;
    const int lr = lane >> 2;
    const int lc = lane & 3;

    float acc[4][8][4];
    #pragma unroll
    for (int i = 0; i < 4; i++)
        #pragma unroll
        for (int j = 0; j < 8; j++)
            #pragma unroll
            for (int q = 0; q < 4; q++) acc[i][j][q] = 0.0f;

    const int KT = K / GBK;

    auto load_tile = [&](int kt, int st) {
        float* As = sm + st * AS_F;
        float* Bs = sm + 2 * AS_F + st * BS_F;
        const int k0 = kt * GBK;
        #pragma unroll
        for (int i = tid; i < GBM * GBK / 4; i += 128) {
            int r = i >> 3, kc = (i & 7) << 2;
            cp_async16(As + r * ASTR + kc, A + (long long)(m0 + r) * lda + k0 + kc);
        }
        #pragma unroll
        for (int i = tid; i < GBK * GBN / 4; i += 128) {
            int r = i >> 5, nc = (i & 31) << 2;
            cp_async16(Bs + r * BSTR + nc, B + (long long)(k0 + r) * ldb + n0 + nc);
        }
        cp_commit();
    };

    load_tile(0, 0);

    for (int kt = 0; kt < KT; kt++) {
        const int buf = kt & 1;
        if (kt + 1 < KT) { load_tile(kt + 1, buf ^ 1); cp_wait<1>(); }
        else             { cp_wait<0>(); }
        __syncthreads();

        const float* As = sm + buf * AS_F;
        const float* Bs = sm + 2 * AS_F + buf * BS_F;

        #pragma unroll
        for (int kq = 0; kq < GBK; kq += 8) {
            uint32_t afr[4][4];
            #pragma unroll
            for (int im = 0; im < 4; im++) {
                const float* Ab = As + (wm + im * 16 + lr) * ASTR + kq + lc;
                afr[im][0] = f2tf32(Ab[0]);
                afr[im][1] = f2tf32(Ab[8 * ASTR]);
                afr[im][2] = f2tf32(Ab[4]);
                afr[im][3] = f2tf32(Ab[8 * ASTR + 4]);
            }
            #pragma unroll
            for (int jn = 0; jn < 8; jn++) {
                const float* Bb = Bs + (kq + lc) * BSTR + wn + jn * 8 + lr;
                uint32_t bfr[2];
                bfr[0] = f2tf32(Bb[0]);
                bfr[1] = f2tf32(Bb[4 * BSTR]);
                #pragma unroll
                for (int im = 0; im < 4; im++) mma_tf32(acc[im][jn], afr[im], bfr);
            }
        }
        __syncthreads();
    }

    #pragma unroll
    for (int im = 0; im < 4; im++) {
        const int r0 = m0 + wm + im * 16 + lr;
        #pragma unroll
        for (int jn = 0; jn < 8; jn++) {
            const int cb = n0 + wn + jn * 8 + lc * 2;
            float bv0 = bias[cb], bv1 = bias[cb + 1];
            #pragma unroll
            for (int hf = 0; hf < 2; hf++) {
                const int r = r0 + hf * 8;
                float v0 = acc[im][jn][hf * 2]     + bv0;
                float v1 = acc[im][jn][hf * 2 + 1] + bv1;
                if (EPI == 2) { v0 = gelu_tanh(v0); v1 = gelu_tanh(v1); }
                if (EPI == 3) {
                    const float* rp = res + (long long)r * ldc + cb;
                    v0 += rp[0]; v1 += rp[1];
                }
                float* cp = C + (long long)r * ldc + cb;
                cp[0] = v0; cp[1] = v1;
            }
        }
    }
}

// ---------------------------------------------------------------------------
extern "C" void kernel_launch(void* const* d_in, const int* in_sizes, int n_in,
                              void* d_out, int out_size) {
    const float* x     = (const float*)d_in[0];
    const float* ln1g  = (const float*)d_in[1];
    const float* ln1b  = (const float*)d_in[2];
    const float* Wqkv  = (const float*)d_in[3];
    const float* bqkv  = (const float*)d_in[4];
    const float* Wproj = (const float*)d_in[5];
    const float* bproj = (const float*)d_in[6];
    const float* ln2g  = (const float*)d_in[7];
    const float* ln2b  = (const float*)d_in[8];
    const float* Wfc   = (const float*)d_in[9];
    const float* bfc   = (const float*)d_in[10];
    const float* Wout  = (const float*)d_in[11];
    const float* bout  = (const float*)d_in[12];
    float* out = (float*)d_out;

    float *xn, *qkv, *ycat, *hbuf;
    cudaGetSymbolAddress((void**)&xn,   g_xn);
    cudaGetSymbolAddress((void**)&qkv,  g_qkv);
    cudaGetSymbolAddress((void**)&ycat, g_ycat);
    cudaGetSymbolAddress((void**)&hbuf, g_h);

    const int gsmem = G_SMEM_F * sizeof(float);   // 70 KB
    const int fsmem = FL_SMEM_F * sizeof(float);  // ~103 KB
    static bool attr_done = false;
    if (!attr_done) {
        cudaFuncSetAttribute(mma_gemm<1>, cudaFuncAttributeMaxDynamicSharedMemorySize, gsmem);
        cudaFuncSetAttribute(mma_gemm<2>, cudaFuncAttributeMaxDynamicSharedMemorySize, gsmem);
        cudaFuncSetAttribute(mma_gemm<3>, cudaFuncAttributeMaxDynamicSharedMemorySize, gsmem);
        cudaFuncSetAttribute(flash_kernel, cudaFuncAttributeMaxDynamicSharedMemorySize, fsmem);
        attr_done = true;
    }

    // 1) LN1
    ln_kernel<<<RROWS, 256>>>(x, ln1g, ln1b, xn);

    // 2) QKV = LN1(x) @ Wqkv + bqkv
    mma_gemm<1><<<dim3(3 * EDIM / GBN, RROWS / GBM), 128, gsmem>>>(
        EDIM, xn, EDIM, Wqkv, 3 * EDIM, qkv, 3 * EDIM, bqkv, nullptr);

    // 3) flash attention -> ycat
    flash_kernel<<<dim3(TSEQ / 128, HEADS, BATCH), 128, fsmem>>>(qkv, ycat);

    // 4) x1 = x + ycat @ Wproj + bproj -> d_out
    mma_gemm<3><<<dim3(EDIM / GBN, RROWS / GBM), 128, gsmem>>>(
        EDIM, ycat, EDIM, Wproj, EDIM, out, EDIM, bproj, x);

    // 5) LN2(x1) -> xn
    ln_kernel<<<RROWS, 256>>>(out, ln2g, ln2b, xn);

    // 6) h = gelu(xn @ Wfc + bfc)
    mma_gemm<2><<<dim3(HID / GBN, RROWS / GBM), 128, gsmem>>>(
        EDIM, xn, EDIM, Wfc, HID, hbuf, HID, bfc, nullptr);

    // 7) out = x1 + h @ Wout + bout
    mma_gemm<3><<<dim3(EDIM / GBN, RROWS / GBM), 128, gsmem>>>(
        HID, hbuf, HID, Wout, EDIM, out, EDIM, bout, out);
}

// round 7
// speedup vs baseline: 1.4333x; 1.4333x over previous
#include <cuda_runtime.h>
#include <cuda_bf16.h>
#include <cstdint>

// ---------------------------------------------------------------------------
// TransformerBlock B=8,T=1024,E=1024,H=16,HD=64,HID=4096 fp32.
// R6: R4 config (256x128x16 GEMM tile, 8 warps x 64x64, 3-stage cp.async;
// flash double-buffered) with the tf32 CVT removed from all inner loops:
// MMA consumes raw f32 bits (tf32 truncation, CUTLASS-style).
// ---------------------------------------------------------------------------

#define RROWS 8192
#define EDIM  1024
#define HEADS 16
#define HD    64
#define HID   4096
#define TSEQ  1024
#define BATCH 8

__device__ float g_xn  [RROWS * EDIM];
__device__ float g_qkv [RROWS * 3 * EDIM];
__device__ float g_ycat[RROWS * EDIM];
__device__ float g_h   [RROWS * HID];

__device__ __forceinline__ float gelu_tanh(float x) {
    float x3 = x * x * x;
    return 0.5f * x * (1.0f + tanhf(0.7978845608028654f * (x + 0.044715f * x3)));
}
__device__ __forceinline__ void cp_async16(void* smem_dst, const void* gsrc) {
    uint32_t d = (uint32_t)__cvta_generic_to_shared(smem_dst);
    asm volatile("cp.async.cg.shared.global [%0], [%1], 16;\n" :: "r"(d), "l"(gsrc));
}
__device__ __forceinline__ void cp_commit() { asm volatile("cp.async.commit_group;\n"); }
template <int N>
__device__ __forceinline__ void cp_wait() { asm volatile("cp.async.wait_group %0;\n" :: "n"(N)); }

__device__ __forceinline__ void mma_tf32(float* c, const uint32_t* a, const uint32_t* b) {
    asm volatile(
        "mma.sync.aligned.m16n8k8.row.col.f32.tf32.tf32.f32 "
        "{%0,%1,%2,%3}, {%4,%5,%6,%7}, {%8,%9}, {%0,%1,%2,%3};"
        : "+f"(c[0]), "+f"(c[1]), "+f"(c[2]), "+f"(c[3])
        : "r"(a[0]), "r"(a[1]), "r"(a[2]), "r"(a[3]), "r"(b[0]), "r"(b[1]));
}

// ---------------------------------------------------------------------------
// LayerNorm: one block (256 threads) per 1024-col row.
// ---------------------------------------------------------------------------
__global__ void ln_kernel(const float* __restrict__ x,
                          const float* __restrict__ g,
                          const float* __restrict__ b,
                          float* __restrict__ out) {
    __shared__ float red[8];
    const long long row = blockIdx.x;
    const int t = threadIdx.x;
    float4 v = ((const float4*)(x + row * EDIM))[t];

    float s = v.x + v.y + v.z + v.w;
    #pragma unroll
    for (int o = 16; o; o >>= 1) s += __shfl_xor_sync(~0u, s, o);
    if ((t & 31) == 0) red[t >> 5] = s;
    __syncthreads();
    if (t < 8) {
        s = red[t];
        #pragma unroll
        for (int o = 4; o; o >>= 1) s += __shfl_xor_sync(0xffu, s, o);
        if (t == 0) red[0] = s;
    }
    __syncthreads();
    const float mean = red[0] * (1.0f / EDIM);

    float dx = v.x - mean, dy = v.y - mean, dz = v.z - mean, dw = v.w - mean;
    float q = dx * dx + dy * dy + dz * dz + dw * dw;
    #pragma unroll
    for (int o = 16; o; o >>= 1) q += __shfl_xor_sync(~0u, q, o);
    __syncthreads();
    if ((t & 31) == 0) red[t >> 5] = q;
    __syncthreads();
    if (t < 8) {
        q = red[t];
        #pragma unroll
        for (int o = 4; o; o >>= 1) q += __shfl_xor_sync(0xffu, q, o);
        if (t == 0) red[0] = q;
    }
    __syncthreads();
    const float rstd = rsqrtf(red[0] * (1.0f / EDIM) + 1e-5f);

    const float4 gg = ((const float4*)g)[t];
    const float4 bb = ((const float4*)b)[t];
    float4 o4;
    o4.x = dx * rstd * gg.x + bb.x;
    o4.y = dy * rstd * gg.y + bb.y;
    o4.z = dz * rstd * gg.z + bb.z;
    o4.w = dw * rstd * gg.w + bb.w;
    ((float4*)(out + row * EDIM))[t] = o4;
}

// ---------------------------------------------------------------------------
// Flash attention, non-causal. One CTA = 128 q-rows of one (b,h).
// 4 warps; key tiles of 64, double-buffered cp.async. Raw-bit tf32 MMA.
// ---------------------------------------------------------------------------
#define KSTR 68
#define VSTR 72
#define FL_QOFF 0
#define FL_KOFF (128 * KSTR)
#define FL_VOFF (FL_KOFF + 2 * 64 * KSTR)
#define FL_POFF (FL_VOFF + 2 * 64 * VSTR)
#define FL_SMEM_F (FL_POFF + 128 * KSTR)

__global__ void __launch_bounds__(128)
flash_kernel(const float* __restrict__ qkv, float* __restrict__ ycat) {
    extern __shared__ float sm[];
    float* Qsm = sm + FL_QOFF;
    float* Psm = sm + FL_POFF;

    const int tid  = threadIdx.x;
    const int lane = tid & 31;
    const int warp = tid >> 5;
    const int lr = lane >> 2;
    const int lc = lane & 3;
    const int q0 = blockIdx.x * 128;
    const int h  = blockIdx.y;
    const int b  = blockIdx.z;
    const int wm = warp * 32;

    const float* qkvb = qkv + (long long)b * TSEQ * 3 * EDIM;
    const float* Qg = qkvb + h * HD;
    const float* Kg = qkvb + EDIM + h * HD;
    const float* Vg = qkvb + 2 * EDIM + h * HD;

    #pragma unroll
    for (int i = tid; i < 128 * 16; i += 128) {
        int r = i >> 4, c4 = (i & 15) << 2;
        float4 v = *(const float4*)(Qg + (long long)(q0 + r) * 3 * EDIM + c4);
        float* d = Qsm + r * KSTR + c4;
        d[0] = v.x * 0.125f; d[1] = v.y * 0.125f; d[2] = v.z * 0.125f; d[3] = v.w * 0.125f;
    }

    auto load_kv = [&](int j, int buf) {
        float* Ks = sm + FL_KOFF + buf * 64 * KSTR;
        float* Vs = sm + FL_VOFF + buf * 64 * VSTR;
        const float* Kj = Kg + (long long)(j * 64) * 3 * EDIM;
        const float* Vj = Vg + (long long)(j * 64) * 3 * EDIM;
        #pragma unroll
        for (int i = tid; i < 64 * 16; i += 128) {
            int r = i >> 4, c4 = (i & 15) << 2;
            cp_async16(Ks + r * KSTR + c4, Kj + (long long)r * 3 * EDIM + c4);
            cp_async16(Vs + r * VSTR + c4, Vj + (long long)r * 3 * EDIM + c4);
        }
        cp_commit();
    };

    float o[2][8][4];
    float m[2][2], l[2][2];
    #pragma unroll
    for (int im = 0; im < 2; im++) {
        #pragma unroll
        for (int jn = 0; jn < 8; jn++)
            #pragma unroll
            for (int q = 0; q < 4; q++) o[im][jn][q] = 0.0f;
        m[im][0] = m[im][1] = -1e30f;
        l[im][0] = l[im][1] = 0.0f;
    }

    load_kv(0, 0);

    const int NT = TSEQ / 64;
    for (int j = 0; j < NT; j++) {
        const int buf = j & 1;
        if (j + 1 < NT) { load_kv(j + 1, buf ^ 1); cp_wait<1>(); }
        else           { cp_wait<0>(); }
        __syncthreads();

        const float* Ks = sm + FL_KOFF + buf * 64 * KSTR;
        const float* Vs = sm + FL_VOFF + buf * 64 * VSTR;

        // ---- S = Q K^T ----
        float s[2][8][4];
        #pragma unroll
        for (int im = 0; im < 2; im++)
            #pragma unroll
            for (int jn = 0; jn < 8; jn++)
                #pragma unroll
                for (int q = 0; q < 4; q++) s[im][jn][q] = 0.0f;

        #pragma unroll
        for (int kq = 0; kq < HD; kq += 8) {
            uint32_t afr[2][4];
            #pragma unroll
            for (int im = 0; im < 2; im++) {
                const uint32_t* Ab = (const uint32_t*)(Qsm + (wm + im * 16 + lr) * KSTR + kq + lc);
                afr[im][0] = Ab[0];
                afr[im][1] = Ab[8 * KSTR];
                afr[im][2] = Ab[4];
                afr[im][3] = Ab[8 * KSTR + 4];
            }
            #pragma unroll
            for (int jn = 0; jn < 8; jn++) {
                const uint32_t* Bb = (const uint32_t*)(Ks + (jn * 8 + lr) * KSTR + kq + lc);
                uint32_t bfr[2];
                bfr[0] = Bb[0];
                bfr[1] = Bb[4];
                #pragma unroll
                for (int im = 0; im < 2; im++) mma_tf32(s[im][jn], afr[im], bfr);
            }
        }

        // ---- online softmax; write P (own rows) ----
        #pragma unroll
        for (int im = 0; im < 2; im++) {
            #pragma unroll
            for (int hf = 0; hf < 2; hf++) {
                float mx = -1e30f;
                #pragma unroll
                for (int jn = 0; jn < 8; jn++)
                    mx = fmaxf(mx, fmaxf(s[im][jn][hf * 2], s[im][jn][hf * 2 + 1]));
                mx = fmaxf(mx, __shfl_xor_sync(~0u, mx, 1));
                mx = fmaxf(mx, __shfl_xor_sync(~0u, mx, 2));
                const float mnew = fmaxf(m[im][hf], mx);
                const float alpha = __expf(m[im][hf] - mnew);
                m[im][hf] = mnew;
                const int prow = wm + im * 16 + hf * 8 + lr;
                float sum = 0.0f;
                #pragma unroll
                for (int jn = 0; jn < 8; jn++) {
                    float p0 = __expf(s[im][jn][hf * 2]     - mnew);
                    float p1 = __expf(s[im][jn][hf * 2 + 1] - mnew);
                    sum += p0 + p1;
                    *(float2*)(Psm + prow * KSTR + jn * 8 + 2 * lc) = make_float2(p0, p1);
                }
                sum += __shfl_xor_sync(~0u, sum, 1);
                sum += __shfl_xor_sync(~0u, sum, 2);
                l[im][hf] = l[im][hf] * alpha + sum;
                #pragma unroll
                for (int jn = 0; jn < 8; jn++) {
                    o[im][jn][hf * 2]     *= alpha;
                    o[im][jn][hf * 2 + 1] *= alpha;
                }
            }
        }
        __syncwarp();

        // ---- O += P @ V ----
        #pragma unroll
        for (int kq = 0; kq < 64; kq += 8) {
            uint32_t afr[2][4];
            #pragma unroll
            for (int im = 0; im < 2; im++) {
                const uint32_t* Ab = (const uint32_t*)(Psm + (wm + im * 16 + lr) * KSTR + kq + lc);
                afr[im][0] = Ab[0];
                afr[im][1] = Ab[8 * KSTR];
                afr[im][2] = Ab[4];
                afr[im][3] = Ab[8 * KSTR + 4];
            }
            #pragma unroll
            for (int jn = 0; jn < 8; jn++) {
                const uint32_t* Bb = (const uint32_t*)(Vs + (kq + lc) * VSTR + jn * 8 + lr);
                uint32_t bfr[2];
                bfr[0] = Bb[0];
                bfr[1] = Bb[4 * VSTR];
                #pragma unroll
                for (int im = 0; im < 2; im++) mma_tf32(o[im][jn], afr[im], bfr);
            }
        }
        __syncthreads();
    }

    #pragma unroll
    for (int im = 0; im < 2; im++) {
        #pragma unroll
        for (int hf = 0; hf < 2; hf++) {
            const float inv = 1.0f / l[im][hf];
            const long long row = (long long)b * TSEQ + q0 + wm + im * 16 + hf * 8 + lr;
            #pragma unroll
            for (int jn = 0; jn < 8; jn++) {
                *(float2*)(ycat + row * EDIM + h * HD + jn * 8 + 2 * lc) =
                    make_float2(o[im][jn][hf * 2] * inv, o[im][jn][hf * 2 + 1] * inv);
            }
        }
    }
}

// ---------------------------------------------------------------------------
// TF32 GEMM: 256x128x16 CTA tile, 8 warps x (64x64), 3-stage cp.async.
// Raw-bit tf32 fragments (no CVT in inner loop).
//   EPI: 1 +bias, 2 +bias,GELU, 3 +bias,+res (stride ldc).
// ---------------------------------------------------------------------------
#define GBM 256
#define GBN 128
#define GBK 16
#define ASTR 20     // GBK+4
#define BSTR 136    // GBN+8
#define AS_F (GBM * ASTR)
#define BS_F (GBK * BSTR)
#define G_SMEM_F (3 * (AS_F + BS_F))

template <int EPI>
__global__ void __launch_bounds__(256)
mma_gemm(int K,
         const float* __restrict__ A, int lda,
         const float* __restrict__ B, int ldb,
         float* __restrict__ C, int ldc,
         const float* __restrict__ bias,
         const float* __restrict__ res) {
    extern __shared__ float sm[];
    const int m0 = blockIdx.y * GBM;
    const int n0 = blockIdx.x * GBN;
    const int tid  = threadIdx.x;
    const int lane = tid & 31;
    const int warp = tid >> 5;
    const int wm = (warp >> 1) * 64;
    const int wn = (warp & 1) * 64;
    const int lr = lane >> 2;
    const int lc = lane & 3;

    float acc[4][8][4];
    #pragma unroll
    for (int i = 0; i < 4; i++)
        #pragma unroll
        for (int j = 0; j < 8; j++)
            #pragma unroll
            for (int q = 0; q < 4; q++) acc[i][j][q] = 0.0f;

    const int KT = K / GBK;

    auto load_tile = [&](int kt, int st) {
        float* As = sm + st * AS_F;
        float* Bs = sm + 3 * AS_F + st * BS_F;
        const int k0 = kt * GBK;
        #pragma unroll
        for (int i = tid; i < GBM * GBK / 4; i += 256) {
            int r = i >> 2, kc = (i & 3) << 2;
            cp_async16(As + r * ASTR + kc, A + (long long)(m0 + r) * lda + k0 + kc);
        }
        #pragma unroll
        for (int i = tid; i < GBK * GBN / 4; i += 256) {
            int r = i >> 5, nc = (i & 31) << 2;
            cp_async16(Bs + r * BSTR + nc, B + (long long)(k0 + r) * ldb + n0 + nc);
        }
        cp_commit();
    };

    load_tile(0, 0);
    load_tile(1, 1);

    int st = 0;
    for (int kt = 0; kt < KT; kt++) {
        cp_wait<1>();
        __syncthreads();
        if (kt + 2 < KT) {
            int st2 = st + 2; if (st2 >= 3) st2 -= 3;
            load_tile(kt + 2, st2);
        }
        const float* As = sm + st * AS_F;
        const float* Bs = sm + 3 * AS_F + st * BS_F;

        #pragma unroll
        for (int kq = 0; kq < GBK; kq += 8) {
            uint32_t afr[4][4];
            #pragma unroll
            for (int im = 0; im < 4; im++) {
                const uint32_t* Ab = (const uint32_t*)(As + (wm + im * 16 + lr) * ASTR + kq + lc);
                afr[im][0] = Ab[0];
                afr[im][1] = Ab[8 * ASTR];
                afr[im][2] = Ab[4];
                afr[im][3] = Ab[8 * ASTR + 4];
            }
            #pragma unroll
            for (int jn = 0; jn < 8; jn++) {
                const uint32_t* Bb = (const uint32_t*)(Bs + (kq + lc) * BSTR + wn + jn * 8 + lr);
                uint32_t bfr[2];
                bfr[0] = Bb[0];
                bfr[1] = Bb[4 * BSTR];
                #pragma unroll
                for (int im = 0; im < 4; im++) mma_tf32(acc[im][jn], afr[im], bfr);
            }
        }
        __syncthreads();
        if (++st == 3) st = 0;
    }

    #pragma unroll
    for (int im = 0; im < 4; im++) {
        const int r0 = m0 + wm + im * 16 + lr;
        #pragma unroll
        for (int jn = 0; jn < 8; jn++) {
            const int cb = n0 + wn + jn * 8 + lc * 2;
            float bv0 = bias[cb], bv1 = bias[cb + 1];
            #pragma unroll
            for (int hf = 0; hf < 2; hf++) {
                const int r = r0 + hf * 8;
                float v0 = acc[im][jn][hf * 2]     + bv0;
                float v1 = acc[im][jn][hf * 2 + 1] + bv1;
                if (EPI == 2) { v0 = gelu_tanh(v0); v1 = gelu_tanh(v1); }
                if (EPI == 3) {
                    const float* rp = res + (long long)r * ldc + cb;
                    v0 += rp[0]; v1 += rp[1];
                }
                float* cp = C + (long long)r * ldc + cb;
                cp[0] = v0; cp[1] = v1;
            }
        }
    }
}

// ---------------------------------------------------------------------------
extern "C" void kernel_launch(void* const* d_in, const int* in_sizes, int n_in,
                              void* d_out, int out_size) {
    const float* x     = (const float*)d_in[0];
    const float* ln1g  = (const float*)d_in[1];
    const float* ln1b  = (const float*)d_in[2];
    const float* Wqkv  = (const float*)d_in[3];
    const float* bqkv  = (const float*)d_in[4];
    const float* Wproj = (const float*)d_in[5];
    const float* bproj = (const float*)d_in[6];
    const float* ln2g  = (const float*)d_in[7];
    const float* ln2b  = (const float*)d_in[8];
    const float* Wfc   = (const float*)d_in[9];
    const float* bfc   = (const float*)d_in[10];
    const float* Wout  = (const float*)d_in[11];
    const float* bout  = (const float*)d_in[12];
    float* out = (float*)d_out;

    float *xn, *qkv, *ycat, *hbuf;
    cudaGetSymbolAddress((void**)&xn,   g_xn);
    cudaGetSymbolAddress((void**)&qkv,  g_qkv);
    cudaGetSymbolAddress((void**)&ycat, g_ycat);
    cudaGetSymbolAddress((void**)&hbuf, g_h);

    const int gsmem = G_SMEM_F * sizeof(float);   // ~87.5 KB
    const int fsmem = FL_SMEM_F * sizeof(float);  // ~138 KB
    static bool attr_done = false;
    if (!attr_done) {
        cudaFuncSetAttribute(mma_gemm<1>, cudaFuncAttributeMaxDynamicSharedMemorySize, gsmem);
        cudaFuncSetAttribute(mma_gemm<2>, cudaFuncAttributeMaxDynamicSharedMemorySize, gsmem);
        cudaFuncSetAttribute(mma_gemm<3>, cudaFuncAttributeMaxDynamicSharedMemorySize, gsmem);
        cudaFuncSetAttribute(flash_kernel, cudaFuncAttributeMaxDynamicSharedMemorySize, fsmem);
        attr_done = true;
    }

    // 1) LN1
    ln_kernel<<<RROWS, 256>>>(x, ln1g, ln1b, xn);

    // 2) QKV = LN1(x) @ Wqkv + bqkv
    mma_gemm<1><<<dim3(3 * EDIM / GBN, RROWS / GBM), 256, gsmem>>>(
        EDIM, xn, EDIM, Wqkv, 3 * EDIM, qkv, 3 * EDIM, bqkv, nullptr);

    // 3) flash attention -> ycat
    flash_kernel<<<dim3(TSEQ / 128, HEADS, BATCH), 128, fsmem>>>(qkv, ycat);

    // 4) x1 = x + ycat @ Wproj + bproj -> d_out
    mma_gemm<3><<<dim3(EDIM / GBN, RROWS / GBM), 256, gsmem>>>(
        EDIM, ycat, EDIM, Wproj, EDIM, out, EDIM, bproj, x);

    // 5) LN2(x1) -> xn
    ln_kernel<<<RROWS, 256>>>(out, ln2g, ln2b, xn);

    // 6) h = gelu(xn @ Wfc + bfc)
    mma_gemm<2><<<dim3(HID / GBN, RROWS / GBM), 256, gsmem>>>(
        EDIM, xn, EDIM, Wfc, HID, hbuf, HID, bfc, nullptr);

    // 7) out = x1 + h @ Wout + bout
    mma_gemm<3><<<dim3(EDIM / GBN, RROWS / GBM), 256, gsmem>>>(
        HID, hbuf, HID, Wout, EDIM, out, EDIM, bout, out);
}

// round 8
// speedup vs baseline: 1.5192x; 1.0599x over previous
#include <cuda_runtime.h>
#include <cuda_bf16.h>
#include <cstdint>

// ---------------------------------------------------------------------------
// TransformerBlock B=8,T=1024,E=1024,H=16,HD=64,HID=4096 fp32.
// R7: producer-side tf32 RNA rounding (weights pre-rounded into scratch,
// activations rounded at store) so inner loops stay CVT-free at full RNA
// precision; GEMM warp tile 64x32 + __launch_bounds__(256,2) -> 16 warps/SM.
// ---------------------------------------------------------------------------

#define RROWS 8192
#define EDIM  1024
#define HEADS 16
#define HD    64
#define HID   4096
#define TSEQ  1024
#define BATCH 8

__device__ float g_xn  [RROWS * EDIM];
__device__ float g_qkv [RROWS * 3 * EDIM];
__device__ float g_ycat[RROWS * EDIM];
__device__ float g_h   [RROWS * HID];
__device__ float g_wr  [12582912];   // rounded weights: Wqkv|Wproj|Wfc|Wout

#define WR_QKV  0
#define WR_PROJ 3145728
#define WR_FC   4194304
#define WR_OUT  8388608

__device__ __forceinline__ float gelu_tanh(float x) {
    float x3 = x * x * x;
    return 0.5f * x * (1.0f + tanhf(0.7978845608028654f * (x + 0.044715f * x3)));
}
__device__ __forceinline__ float rnd_tf32(float x) {
    uint32_t r;
    asm("cvt.rna.tf32.f32 %0, %1;" : "=r"(r) : "f"(x));
    return __uint_as_float(r);
}
__device__ __forceinline__ void cp_async16(void* smem_dst, const void* gsrc) {
    uint32_t d = (uint32_t)__cvta_generic_to_shared(smem_dst);
    asm volatile("cp.async.cg.shared.global [%0], [%1], 16;\n" :: "r"(d), "l"(gsrc));
}
__device__ __forceinline__ void cp_commit() { asm volatile("cp.async.commit_group;\n"); }
template <int N>
__device__ __forceinline__ void cp_wait() { asm volatile("cp.async.wait_group %0;\n" :: "n"(N)); }

__device__ __forceinline__ void mma_tf32(float* c, const uint32_t* a, const uint32_t* b) {
    asm volatile(
        "mma.sync.aligned.m16n8k8.row.col.f32.tf32.tf32.f32 "
        "{%0,%1,%2,%3}, {%4,%5,%6,%7}, {%8,%9}, {%0,%1,%2,%3};"
        : "+f"(c[0]), "+f"(c[1]), "+f"(c[2]), "+f"(c[3])
        : "r"(a[0]), "r"(a[1]), "r"(a[2]), "r"(a[3]), "r"(b[0]), "r"(b[1]));
}

// ---------------------------------------------------------------------------
// Weight rounding: fp32 -> tf32(RNA) elementwise, float4 grid-stride.
// ---------------------------------------------------------------------------
__global__ void round_w_kernel(const float* __restrict__ in, float* __restrict__ outp, int n4) {
    int i = blockIdx.x * 256 + threadIdx.x;
    if (i < n4) {
        float4 v = ((const float4*)in)[i];
        v.x = rnd_tf32(v.x); v.y = rnd_tf32(v.y);
        v.z = rnd_tf32(v.z); v.w = rnd_tf32(v.w);
        ((float4*)outp)[i] = v;
    }
}

// ---------------------------------------------------------------------------
// LayerNorm: one block (256 threads) per 1024-col row. Output tf32-rounded.
// ---------------------------------------------------------------------------
__global__ void ln_kernel(const float* __restrict__ x,
                          const float* __restrict__ g,
                          const float* __restrict__ b,
                          float* __restrict__ out) {
    __shared__ float red[8];
    const long long row = blockIdx.x;
    const int t = threadIdx.x;
    float4 v = ((const float4*)(x + row * EDIM))[t];

    float s = v.x + v.y + v.z + v.w;
    #pragma unroll
    for (int o = 16; o; o >>= 1) s += __shfl_xor_sync(~0u, s, o);
    if ((t & 31) == 0) red[t >> 5] = s;
    __syncthreads();
    if (t < 8) {
        s = red[t];
        #pragma unroll
        for (int o = 4; o; o >>= 1) s += __shfl_xor_sync(0xffu, s, o);
        if (t == 0) red[0] = s;
    }
    __syncthreads();
    const float mean = red[0] * (1.0f / EDIM);

    float dx = v.x - mean, dy = v.y - mean, dz = v.z - mean, dw = v.w - mean;
    float q = dx * dx + dy * dy + dz * dz + dw * dw;
    #pragma unroll
    for (int o = 16; o; o >>= 1) q += __shfl_xor_sync(~0u, q, o);
    __syncthreads();
    if ((t & 31) == 0) red[t >> 5] = q;
    __syncthreads();
    if (t < 8) {
        q = red[t];
        #pragma unroll
        for (int o = 4; o; o >>= 1) q += __shfl_xor_sync(0xffu, q, o);
        if (t == 0) red[0] = q;
    }
    __syncthreads();
    const float rstd = rsqrtf(red[0] * (1.0f / EDIM) + 1e-5f);

    const float4 gg = ((const float4*)g)[t];
    const float4 bb = ((const float4*)b)[t];
    float4 o4;
    o4.x = rnd_tf32(dx * rstd * gg.x + bb.x);
    o4.y = rnd_tf32(dy * rstd * gg.y + bb.y);
    o4.z = rnd_tf32(dz * rstd * gg.z + bb.z);
    o4.w = rnd_tf32(dw * rstd * gg.w + bb.w);
    ((float4*)(out + row * EDIM))[t] = o4;
}

// ---------------------------------------------------------------------------
// Flash attention, non-causal. One CTA = 128 q-rows of one (b,h).
// 4 warps; key tiles of 64, double-buffered cp.async. Inputs pre-rounded;
// P rounded at smem store; output rounded (feeds Wproj GEMM).
// ---------------------------------------------------------------------------
#define KSTR 68
#define VSTR 72
#define FL_QOFF 0
#define FL_KOFF (128 * KSTR)
#define FL_VOFF (FL_KOFF + 2 * 64 * KSTR)
#define FL_POFF (FL_VOFF + 2 * 64 * VSTR)
#define FL_SMEM_F (FL_POFF + 128 * KSTR)

__global__ void __launch_bounds__(128)
flash_kernel(const float* __restrict__ qkv, float* __restrict__ ycat) {
    extern __shared__ float sm[];
    float* Qsm = sm + FL_QOFF;
    float* Psm = sm + FL_POFF;

    const int tid  = threadIdx.x;
    const int lane = tid & 31;
    const int warp = tid >> 5;
    const int lr = lane >> 2;
    const int lc = lane & 3;
    const int q0 = blockIdx.x * 128;
    const int h  = blockIdx.y;
    const int b  = blockIdx.z;
    const int wm = warp * 32;

    const float* qkvb = qkv + (long long)b * TSEQ * 3 * EDIM;
    const float* Qg = qkvb + h * HD;
    const float* Kg = qkvb + EDIM + h * HD;
    const float* Vg = qkvb + 2 * EDIM + h * HD;

    // qkv pre-rounded to tf32; *0.125 is an exact exponent shift.
    #pragma unroll
    for (int i = tid; i < 128 * 16; i += 128) {
        int r = i >> 4, c4 = (i & 15) << 2;
        float4 v = *(const float4*)(Qg + (long long)(q0 + r) * 3 * EDIM + c4);
        float* d = Qsm + r * KSTR + c4;
        d[0] = v.x * 0.125f; d[1] = v.y * 0.125f; d[2] = v.z * 0.125f; d[3] = v.w * 0.125f;
    }

    auto load_kv = [&](int j, int buf) {
        float* Ks = sm + FL_KOFF + buf * 64 * KSTR;
        float* Vs = sm + FL_VOFF + buf * 64 * VSTR;
        const float* Kj = Kg + (long long)(j * 64) * 3 * EDIM;
        const float* Vj = Vg + (long long)(j * 64) * 3 * EDIM;
        #pragma unroll
        for (int i = tid; i < 64 * 16; i += 128) {
            int r = i >> 4, c4 = (i & 15) << 2;
            cp_async16(Ks + r * KSTR + c4, Kj + (long long)r * 3 * EDIM + c4);
            cp_async16(Vs + r * VSTR + c4, Vj + (long long)r * 3 * EDIM + c4);
        }
        cp_commit();
    };

    float o[2][8][4];
    float m[2][2], l[2][2];
    #pragma unroll
    for (int im = 0; im < 2; im++) {
        #pragma unroll
        for (int jn = 0; jn < 8; jn++)
            #pragma unroll
            for (int q = 0; q < 4; q++) o[im][jn][q] = 0.0f;
        m[im][0] = m[im][1] = -1e30f;
        l[im][0] = l[im][1] = 0.0f;
    }

    load_kv(0, 0);

    const int NT = TSEQ / 64;
    for (int j = 0; j < NT; j++) {
        const int buf = j & 1;
        if (j + 1 < NT) { load_kv(j + 1, buf ^ 1); cp_wait<1>(); }
        else           { cp_wait<0>(); }
        __syncthreads();

        const float* Ks = sm + FL_KOFF + buf * 64 * KSTR;
        const float* Vs = sm + FL_VOFF + buf * 64 * VSTR;

        // ---- S = Q K^T ----
        float s[2][8][4];
        #pragma unroll
        for (int im = 0; im < 2; im++)
            #pragma unroll
            for (int jn = 0; jn < 8; jn++)
                #pragma unroll
                for (int q = 0; q < 4; q++) s[im][jn][q] = 0.0f;

        #pragma unroll
        for (int kq = 0; kq < HD; kq += 8) {
            uint32_t afr[2][4];
            #pragma unroll
            for (int im = 0; im < 2; im++) {
                const uint32_t* Ab = (const uint32_t*)(Qsm + (wm + im * 16 + lr) * KSTR + kq + lc);
                afr[im][0] = Ab[0];
                afr[im][1] = Ab[8 * KSTR];
                afr[im][2] = Ab[4];
                afr[im][3] = Ab[8 * KSTR + 4];
            }
            #pragma unroll
            for (int jn = 0; jn < 8; jn++) {
                const uint32_t* Bb = (const uint32_t*)(Ks + (jn * 8 + lr) * KSTR + kq + lc);
                uint32_t bfr[2];
                bfr[0] = Bb[0];
                bfr[1] = Bb[4];
                #pragma unroll
                for (int im = 0; im < 2; im++) mma_tf32(s[im][jn], afr[im], bfr);
            }
        }

        // ---- online softmax; write tf32-rounded P (own rows) ----
        #pragma unroll
        for (int im = 0; im < 2; im++) {
            #pragma unroll
            for (int hf = 0; hf < 2; hf++) {
                float mx = -1e30f;
                #pragma unroll
                for (int jn = 0; jn < 8; jn++)
                    mx = fmaxf(mx, fmaxf(s[im][jn][hf * 2], s[im][jn][hf * 2 + 1]));
                mx = fmaxf(mx, __shfl_xor_sync(~0u, mx, 1));
                mx = fmaxf(mx, __shfl_xor_sync(~0u, mx, 2));
                const float mnew = fmaxf(m[im][hf], mx);
                const float alpha = __expf(m[im][hf] - mnew);
                m[im][hf] = mnew;
                const int prow = wm + im * 16 + hf * 8 + lr;
                float sum = 0.0f;
                #pragma unroll
                for (int jn = 0; jn < 8; jn++) {
                    float p0 = __expf(s[im][jn][hf * 2]     - mnew);
                    float p1 = __expf(s[im][jn][hf * 2 + 1] - mnew);
                    sum += p0 + p1;
                    *(float2*)(Psm + prow * KSTR + jn * 8 + 2 * lc) =
                        make_float2(rnd_tf32(p0), rnd_tf32(p1));
                }
                sum += __shfl_xor_sync(~0u, sum, 1);
                sum += __shfl_xor_sync(~0u, sum, 2);
                l[im][hf] = l[im][hf] * alpha + sum;
                #pragma unroll
                for (int jn = 0; jn < 8; jn++) {
                    o[im][jn][hf * 2]     *= alpha;
                    o[im][jn][hf * 2 + 1] *= alpha;
                }
            }
        }
        __syncwarp();

        // ---- O += P @ V ----
        #pragma unroll
        for (int kq = 0; kq < 64; kq += 8) {
            uint32_t afr[2][4];
            #pragma unroll
            for (int im = 0; im < 2; im++) {
                const uint32_t* Ab = (const uint32_t*)(Psm + (wm + im * 16 + lr) * KSTR + kq + lc);
                afr[im][0] = Ab[0];
                afr[im][1] = Ab[8 * KSTR];
                afr[im][2] = Ab[4];
                afr[im][3] = Ab[8 * KSTR + 4];
            }
            #pragma unroll
            for (int jn = 0; jn < 8; jn++) {
                const uint32_t* Bb = (const uint32_t*)(Vs + (kq + lc) * VSTR + jn * 8 + lr);
                uint32_t bfr[2];
                bfr[0] = Bb[0];
                bfr[1] = Bb[4 * VSTR];
                #pragma unroll
                for (int im = 0; im < 2; im++) mma_tf32(o[im][jn], afr[im], bfr);
            }
        }
        __syncthreads();
    }

    // ycat feeds the Wproj GEMM -> round at store.
    #pragma unroll
    for (int im = 0; im < 2; im++) {
        #pragma unroll
        for (int hf = 0; hf < 2; hf++) {
            const float inv = 1.0f / l[im][hf];
            const long long row = (long long)b * TSEQ + q0 + wm + im * 16 + hf * 8 + lr;
            #pragma unroll
            for (int jn = 0; jn < 8; jn++) {
                *(float2*)(ycat + row * EDIM + h * HD + jn * 8 + 2 * lc) =
                    make_float2(rnd_tf32(o[im][jn][hf * 2] * inv),
                                rnd_tf32(o[im][jn][hf * 2 + 1] * inv));
            }
        }
    }
}

// ---------------------------------------------------------------------------
// TF32 GEMM: 128x128x16 CTA tile, 8 warps x (64x32), 3-stage cp.async,
// __launch_bounds__(256,2) -> 2 CTAs/SM (16 warps). Raw-bit tf32 fragments
// (inputs pre-rounded). EPI: 1 +bias, 2 +bias,GELU, 3 +bias,+res.
// RND: round stored output to tf32 (when it feeds another GEMM/flash).
// ---------------------------------------------------------------------------
#define GBM 128
#define GBN 128
#define GBK 16
#define ASTR 20     // GBK+4
#define BSTR 136    // GBN+8
#define AS_F (GBM * ASTR)
#define BS_F (GBK * BSTR)
#define G_SMEM_F (3 * (AS_F + BS_F))

template <int EPI, bool RND>
__global__ void __launch_bounds__(256, 2)
mma_gemm(int K,
         const float* __restrict__ A, int lda,
         const float* __restrict__ B, int ldb,
         float* __restrict__ C, int ldc,
         const float* __restrict__ bias,
         const float* __restrict__ res) {
    extern __shared__ float sm[];
    const int m0 = blockIdx.y * GBM;
    const int n0 = blockIdx.x * GBN;
    const int tid  = threadIdx.x;
    const int lane = tid & 31;
    const int warp = tid >> 5;
    const int wm = (warp >> 2) * 64;     // 2 m-warps
    const int wn = (warp & 3) * 32;      // 4 n-warps
    const int lr = lane >> 2;
    const int lc = lane & 3;

    float acc[4][4][4];
    #pragma unroll
    for (int i = 0; i < 4; i++)
        #pragma unroll
        for (int j = 0; j < 4; j++)
            #pragma unroll
            for (int q = 0; q < 4; q++) acc[i][j][q] = 0.0f;

    const int KT = K / GBK;

    auto load_tile = [&](int kt, int st) {
        float* As = sm + st * AS_F;
        float* Bs = sm + 3 * AS_F + st * BS_F;
        const int k0 = kt * GBK;
        #pragma unroll
        for (int i = tid; i < GBM * GBK / 4; i += 256) {
            int r = i >> 2, kc = (i & 3) << 2;
            cp_async16(As + r * ASTR + kc, A + (long long)(m0 + r) * lda + k0 + kc);
        }
        #pragma unroll
        for (int i = tid; i < GBK * GBN / 4; i += 256) {
            int r = i >> 5, nc = (i & 31) << 2;
            cp_async16(Bs + r * BSTR + nc, B + (long long)(k0 + r) * ldb + n0 + nc);
        }
        cp_commit();
    };

    load_tile(0, 0);
    load_tile(1, 1);

    int st = 0;
    for (int kt = 0; kt < KT; kt++) {
        cp_wait<1>();
        __syncthreads();
        if (kt + 2 < KT) {
            int st2 = st + 2; if (st2 >= 3) st2 -= 3;
            load_tile(kt + 2, st2);
        }
        const float* As = sm + st * AS_F;
        const float* Bs = sm + 3 * AS_F + st * BS_F;

        #pragma unroll
        for (int kq = 0; kq < GBK; kq += 8) {
            uint32_t afr[4][4];
            #pragma unroll
            for (int im = 0; im < 4; im++) {
                const uint32_t* Ab = (const uint32_t*)(As + (wm + im * 16 + lr) * ASTR + kq + lc);
                afr[im][0] = Ab[0];
                afr[im][1] = Ab[8 * ASTR];
                afr[im][2] = Ab[4];
                afr[im][3] = Ab[8 * ASTR + 4];
            }
            #pragma unroll
            for (int jn = 0; jn < 4; jn++) {
                const uint32_t* Bb = (const uint32_t*)(Bs + (kq + lc) * BSTR + wn + jn * 8 + lr);
                uint32_t bfr[2];
                bfr[0] = Bb[0];
                bfr[1] = Bb[4 * BSTR];
                #pragma unroll
                for (int im = 0; im < 4; im++) mma_tf32(acc[im][jn], afr[im], bfr);
            }
        }
        __syncthreads();
        if (++st == 3) st = 0;
    }

    #pragma unroll
    for (int im = 0; im < 4; im++) {
        const int r0 = m0 + wm + im * 16 + lr;
        #pragma unroll
        for (int jn = 0; jn < 4; jn++) {
            const int cb = n0 + wn + jn * 8 + lc * 2;
            float bv0 = bias[cb], bv1 = bias[cb + 1];
            #pragma unroll
            for (int hf = 0; hf < 2; hf++) {
                const int r = r0 + hf * 8;
                float v0 = acc[im][jn][hf * 2]     + bv0;
                float v1 = acc[im][jn][hf * 2 + 1] + bv1;
                if (EPI == 2) { v0 = gelu_tanh(v0); v1 = gelu_tanh(v1); }
                if (EPI == 3) {
                    const float* rp = res + (long long)r * ldc + cb;
                    v0 += rp[0]; v1 += rp[1];
                }
                if (RND) { v0 = rnd_tf32(v0); v1 = rnd_tf32(v1); }
                float* cp = C + (long long)r * ldc + cb;
                cp[0] = v0; cp[1] = v1;
            }
        }
    }
}

// ---------------------------------------------------------------------------
extern "C" void kernel_launch(void* const* d_in, const int* in_sizes, int n_in,
                              void* d_out, int out_size) {
    const float* x     = (const float*)d_in[0];
    const float* ln1g  = (const float*)d_in[1];
    const float* ln1b  = (const float*)d_in[2];
    const float* Wqkv  = (const float*)d_in[3];
    const float* bqkv  = (const float*)d_in[4];
    const float* Wproj = (const float*)d_in[5];
    const float* bproj = (const float*)d_in[6];
    const float* ln2g  = (const float*)d_in[7];
    const float* ln2b  = (const float*)d_in[8];
    const float* Wfc   = (const float*)d_in[9];
    const float* bfc   = (const float*)d_in[10];
    const float* Wout  = (const float*)d_in[11];
    const float* bout  = (const float*)d_in[12];
    float* out = (float*)d_out;

    float *xn, *qkv, *ycat, *hbuf, *wr;
    cudaGetSymbolAddress((void**)&xn,   g_xn);
    cudaGetSymbolAddress((void**)&qkv,  g_qkv);
    cudaGetSymbolAddress((void**)&ycat, g_ycat);
    cudaGetSymbolAddress((void**)&hbuf, g_h);
    cudaGetSymbolAddress((void**)&wr,   g_wr);

    const int gsmem = G_SMEM_F * sizeof(float);   // ~55.7 KB
    const int fsmem = FL_SMEM_F * sizeof(float);  // ~138 KB
    static bool attr_done = false;
    if (!attr_done) {
        cudaFuncSetAttribute(mma_gemm<1,true >, cudaFuncAttributeMaxDynamicSharedMemorySize, gsmem);
        cudaFuncSetAttribute(mma_gemm<2,true >, cudaFuncAttributeMaxDynamicSharedMemorySize, gsmem);
        cudaFuncSetAttribute(mma_gemm<3,false>, cudaFuncAttributeMaxDynamicSharedMemorySize, gsmem);
        cudaFuncSetAttribute(flash_kernel, cudaFuncAttributeMaxDynamicSharedMemorySize, fsmem);
        attr_done = true;
    }

    // 0) round weights to tf32 (idempotent, ~20us)
    round_w_kernel<<<(3145728/4 + 255)/256, 256>>>(Wqkv,  wr + WR_QKV,  3145728/4);
    round_w_kernel<<<(1048576/4 + 255)/256, 256>>>(Wproj, wr + WR_PROJ, 1048576/4);
    round_w_kernel<<<(4194304/4 + 255)/256, 256>>>(Wfc,   wr + WR_FC,   4194304/4);
    round_w_kernel<<<(4194304/4 + 255)/256, 256>>>(Wout,  wr + WR_OUT,  4194304/4);

    // 1) LN1 (tf32-rounded out)
    ln_kernel<<<RROWS, 256>>>(x, ln1g, ln1b, xn);

    // 2) QKV = LN1(x) @ Wqkv + bqkv  (rounded out: feeds flash)
    mma_gemm<1,true><<<dim3(3 * EDIM / GBN, RROWS / GBM), 256, gsmem>>>(
        EDIM, xn, EDIM, wr + WR_QKV, 3 * EDIM, qkv, 3 * EDIM, bqkv, nullptr);

    // 3) flash attention -> ycat (rounded out)
    flash_kernel<<<dim3(TSEQ / 128, HEADS, BATCH), 128, fsmem>>>(qkv, ycat);

    // 4) x1 = x + ycat @ Wproj + bproj -> d_out (full fp32)
    mma_gemm<3,false><<<dim3(EDIM / GBN, RROWS / GBM), 256, gsmem>>>(
        EDIM, ycat, EDIM, wr + WR_PROJ, EDIM, out, EDIM, bproj, x);

    // 5) LN2(x1) -> xn (rounded out)
    ln_kernel<<<RROWS, 256>>>(out, ln2g, ln2b, xn);

    // 6) h = gelu(xn @ Wfc + bfc) (rounded out: feeds Wout GEMM)
    mma_gemm<2,true><<<dim3(HID / GBN, RROWS / GBM), 256, gsmem>>>(
        EDIM, xn, EDIM, wr + WR_FC, HID, hbuf, HID, bfc, nullptr);

    // 7) out = x1 + h @ Wout + bout (full fp32)
    mma_gemm<3,false><<<dim3(EDIM / GBN, RROWS / GBM), 256, gsmem>>>(
        HID, hbuf, HID, wr + WR_OUT, EDIM, out, EDIM, bout, out);
}

// round 11
// speedup vs baseline: 1.5223x; 1.0020x over previous
#include <cuda_runtime.h>
#include <cuda_bf16.h>
#include <cstdint>

// ---------------------------------------------------------------------------
// TransformerBlock B=8,T=1024,E=1024,H=16,HD=64,HID=4096 fp32.
// R9: tcgen05 unavailable (harness compiles family target sm_103, not
// sm_103a) -> stay on legacy tf32 mma. Flash attention widened to 256
// threads / 8 warps per CTA (256 q-rows), double-buffered K/V, 206KB smem:
// 2 warps/SMSP instead of 1. GEMMs/LN/rounding identical to R8 (1799us).
// ---------------------------------------------------------------------------

#define RROWS 8192
#define EDIM  1024
#define HEADS 16
#define HD    64
#define HID   4096
#define TSEQ  1024
#define BATCH 8

__device__ float g_xn  [RROWS * EDIM];
__device__ float g_qkv [RROWS * 3 * EDIM];
__device__ float g_ycat[RROWS * EDIM];
__device__ float g_h   [RROWS * HID];
__device__ float g_wr  [12582912];   // rounded weights: Wqkv|Wproj|Wfc|Wout

#define WR_QKV  0
#define WR_PROJ 3145728
#define WR_FC   4194304
#define WR_OUT  8388608

__device__ __forceinline__ float gelu_tanh(float x) {
    float x3 = x * x * x;
    return 0.5f * x * (1.0f + tanhf(0.7978845608028654f * (x + 0.044715f * x3)));
}
__device__ __forceinline__ float rnd_tf32(float x) {
    uint32_t r;
    asm("cvt.rna.tf32.f32 %0, %1;" : "=r"(r) : "f"(x));
    return __uint_as_float(r);
}
__device__ __forceinline__ void cp_async16(void* smem_dst, const void* gsrc) {
    uint32_t d = (uint32_t)__cvta_generic_to_shared(smem_dst);
    asm volatile("cp.async.cg.shared.global [%0], [%1], 16;\n" :: "r"(d), "l"(gsrc));
}
__device__ __forceinline__ void cp_commit() { asm volatile("cp.async.commit_group;\n"); }
template <int N>
__device__ __forceinline__ void cp_wait() { asm volatile("cp.async.wait_group %0;\n" :: "n"(N)); }

__device__ __forceinline__ void mma_tf32(float* c, const uint32_t* a, const uint32_t* b) {
    asm volatile(
        "mma.sync.aligned.m16n8k8.row.col.f32.tf32.tf32.f32 "
        "{%0,%1,%2,%3}, {%4,%5,%6,%7}, {%8,%9}, {%0,%1,%2,%3};"
        : "+f"(c[0]), "+f"(c[1]), "+f"(c[2]), "+f"(c[3])
        : "r"(a[0]), "r"(a[1]), "r"(a[2]), "r"(a[3]), "r"(b[0]), "r"(b[1]));
}

// ---------------------------------------------------------------------------
// Weight rounding: fp32 -> tf32(RNA) elementwise, float4.
// ---------------------------------------------------------------------------
__global__ void round_w_kernel(const float* __restrict__ in, float* __restrict__ outp, int n4) {
    int i = blockIdx.x * 256 + threadIdx.x;
    if (i < n4) {
        float4 v = ((const float4*)in)[i];
        v.x = rnd_tf32(v.x); v.y = rnd_tf32(v.y);
        v.z = rnd_tf32(v.z); v.w = rnd_tf32(v.w);
        ((float4*)outp)[i] = v;
    }
}

// ---------------------------------------------------------------------------
// LayerNorm: one block (256 threads) per 1024-col row. Output tf32-rounded.
// ---------------------------------------------------------------------------
__global__ void ln_kernel(const float* __restrict__ x,
                          const float* __restrict__ g,
                          const float* __restrict__ b,
                          float* __restrict__ out) {
    __shared__ float red[8];
    const long long row = blockIdx.x;
    const int t = threadIdx.x;
    float4 v = ((const float4*)(x + row * EDIM))[t];

    float s = v.x + v.y + v.z + v.w;
    #pragma unroll
    for (int o = 16; o; o >>= 1) s += __shfl_xor_sync(~0u, s, o);
    if ((t & 31) == 0) red[t >> 5] = s;
    __syncthreads();
    if (t < 8) {
        s = red[t];
        #pragma unroll
        for (int o = 4; o; o >>= 1) s += __shfl_xor_sync(0xffu, s, o);
        if (t == 0) red[0] = s;
    }
    __syncthreads();
    const float mean = red[0] * (1.0f / EDIM);

    float dx = v.x - mean, dy = v.y - mean, dz = v.z - mean, dw = v.w - mean;
    float q = dx * dx + dy * dy + dz * dz + dw * dw;
    #pragma unroll
    for (int o = 16; o; o >>= 1) q += __shfl_xor_sync(~0u, q, o);
    __syncthreads();
    if ((t & 31) == 0) red[t >> 5] = q;
    __syncthreads();
    if (t < 8) {
        q = red[t];
        #pragma unroll
        for (int o = 4; o; o >>= 1) q += __shfl_xor_sync(0xffu, q, o);
        if (t == 0) red[0] = q;
    }
    __syncthreads();
    const float rstd = rsqrtf(red[0] * (1.0f / EDIM) + 1e-5f);

    const float4 gg = ((const float4*)g)[t];
    const float4 bb = ((const float4*)b)[t];
    float4 o4;
    o4.x = rnd_tf32(dx * rstd * gg.x + bb.x);
    o4.y = rnd_tf32(dy * rstd * gg.y + bb.y);
    o4.z = rnd_tf32(dz * rstd * gg.z + bb.z);
    o4.w = rnd_tf32(dw * rstd * gg.w + bb.w);
    ((float4*)(out + row * EDIM))[t] = o4;
}

// ---------------------------------------------------------------------------
// Flash attention, non-causal. One CTA = 256 q-rows of one (b,h), 8 warps
// (warp w owns rows [32w,32w+32)). Key tiles of 64, double-buffered cp.async.
// smem ~206KB -> 1 CTA/SM but 2 warps/SMSP.
// ---------------------------------------------------------------------------
#define KSTR 68
#define VSTR 72
#define FL_QOFF 0
#define FL_KOFF (256 * KSTR)
#define FL_VOFF (FL_KOFF + 2 * 64 * KSTR)
#define FL_POFF (FL_VOFF + 2 * 64 * VSTR)
#define FL_SMEM_F (FL_POFF + 256 * KSTR)

__global__ void __launch_bounds__(256)
flash_kernel(const float* __restrict__ qkv, float* __restrict__ ycat) {
    extern __shared__ float sm[];
    float* Qsm = sm + FL_QOFF;
    float* Psm = sm + FL_POFF;

    const int tid  = threadIdx.x;
    const int lane = tid & 31;
    const int warp = tid >> 5;
    const int lr = lane >> 2;
    const int lc = lane & 3;
    const int q0 = blockIdx.x * 256;
    const int h  = blockIdx.y;
    const int b  = blockIdx.z;
    const int wm = warp * 32;

    const float* qkvb = qkv + (long long)b * TSEQ * 3 * EDIM;
    const float* Qg = qkvb + h * HD;
    const float* Kg = qkvb + EDIM + h * HD;
    const float* Vg = qkvb + 2 * EDIM + h * HD;

    // qkv is tf32-pre-rounded; *0.125 is an exact exponent shift.
    #pragma unroll
    for (int i = tid; i < 256 * 16; i += 256) {
        int r = i >> 4, c4 = (i & 15) << 2;
        float4 v = *(const float4*)(Qg + (long long)(q0 + r) * 3 * EDIM + c4);
        float* d = Qsm + r * KSTR + c4;
        d[0] = v.x * 0.125f; d[1] = v.y * 0.125f; d[2] = v.z * 0.125f; d[3] = v.w * 0.125f;
    }

    auto load_kv = [&](int j, int buf) {
        float* Ks = sm + FL_KOFF + buf * 64 * KSTR;
        float* Vs = sm + FL_VOFF + buf * 64 * VSTR;
        const float* Kj = Kg + (long long)(j * 64) * 3 * EDIM;
        const float* Vj = Vg + (long long)(j * 64) * 3 * EDIM;
        #pragma unroll
        for (int i = tid; i < 64 * 16; i += 256) {
            int r = i >> 4, c4 = (i & 15) << 2;
            cp_async16(Ks + r * KSTR + c4, Kj + (long long)r * 3 * EDIM + c4);
            cp_async16(Vs + r * VSTR + c4, Vj + (long long)r * 3 * EDIM + c4);
        }
        cp_commit();
    };

    float o[2][8][4];
    float m[2][2], l[2][2];
    #pragma unroll
    for (int im = 0; im < 2; im++) {
        #pragma unroll
        for (int jn = 0; jn < 8; jn++)
            #pragma unroll
            for (int q = 0; q < 4; q++) o[im][jn][q] = 0.0f;
        m[im][0] = m[im][1] = -1e30f;
        l[im][0] = l[im][1] = 0.0f;
    }

    load_kv(0, 0);

    const int NT = TSEQ / 64;
    for (int j = 0; j < NT; j++) {
        const int buf = j & 1;
        if (j + 1 < NT) { load_kv(j + 1, buf ^ 1); cp_wait<1>(); }
        else           { cp_wait<0>(); }
        __syncthreads();

        const float* Ks = sm + FL_KOFF + buf * 64 * KSTR;
        const float* Vs = sm + FL_VOFF + buf * 64 * VSTR;

        // ---- S = Q K^T ----
        float s[2][8][4];
        #pragma unroll
        for (int im = 0; im < 2; im++)
            #pragma unroll
            for (int jn = 0; jn < 8; jn++)
                #pragma unroll
                for (int q = 0; q < 4; q++) s[im][jn][q] = 0.0f;

        #pragma unroll
        for (int kq = 0; kq < HD; kq += 8) {
            uint32_t afr[2][4];
            #pragma unroll
            for (int im = 0; im < 2; im++) {
                const uint32_t* Ab = (const uint32_t*)(Qsm + (wm + im * 16 + lr) * KSTR + kq + lc);
                afr[im][0] = Ab[0];
                afr[im][1] = Ab[8 * KSTR];
                afr[im][2] = Ab[4];
                afr[im][3] = Ab[8 * KSTR + 4];
            }
            #pragma unroll
            for (int jn = 0; jn < 8; jn++) {
                const uint32_t* Bb = (const uint32_t*)(Ks + (jn * 8 + lr) * KSTR + kq + lc);
                uint32_t bfr[2];
                bfr[0] = Bb[0];
                bfr[1] = Bb[4];
                #pragma unroll
                for (int im = 0; im < 2; im++) mma_tf32(s[im][jn], afr[im], bfr);
            }
        }

        // ---- online softmax; write tf32-rounded P (own rows) ----
        #pragma unroll
        for (int im = 0; im < 2; im++) {
            #pragma unroll
            for (int hf = 0; hf < 2; hf++) {
                float mx = -1e30f;
                #pragma unroll
                for (int jn = 0; jn < 8; jn++)
                    mx = fmaxf(mx, fmaxf(s[im][jn][hf * 2], s[im][jn][hf * 2 + 1]));
                mx = fmaxf(mx, __shfl_xor_sync(~0u, mx, 1));
                mx = fmaxf(mx, __shfl_xor_sync(~0u, mx, 2));
                const float mnew = fmaxf(m[im][hf], mx);
                const float alpha = __expf(m[im][hf] - mnew);
                m[im][hf] = mnew;
                const int prow = wm + im * 16 + hf * 8 + lr;
                float sum = 0.0f;
                #pragma unroll
                for (int jn = 0; jn < 8; jn++) {
                    float p0 = __expf(s[im][jn][hf * 2]     - mnew);
                    float p1 = __expf(s[im][jn][hf * 2 + 1] - mnew);
                    sum += p0 + p1;
                    *(float2*)(Psm + prow * KSTR + jn * 8 + 2 * lc) =
                        make_float2(rnd_tf32(p0), rnd_tf32(p1));
                }
                sum += __shfl_xor_sync(~0u, sum, 1);
                sum += __shfl_xor_sync(~0u, sum, 2);
                l[im][hf] = l[im][hf] * alpha + sum;
                #pragma unroll
                for (int jn = 0; jn < 8; jn++) {
                    o[im][jn][hf * 2]     *= alpha;
                    o[im][jn][hf * 2 + 1] *= alpha;
                }
            }
        }
        __syncwarp();

        // ---- O += P @ V ----
        #pragma unroll
        for (int kq = 0; kq < 64; kq += 8) {
            uint32_t afr[2][4];
            #pragma unroll
            for (int im = 0; im < 2; im++) {
                const uint32_t* Ab = (const uint32_t*)(Psm + (wm + im * 16 + lr) * KSTR + kq + lc);
                afr[im][0] = Ab[0];
                afr[im][1] = Ab[8 * KSTR];
                afr[im][2] = Ab[4];
                afr[im][3] = Ab[8 * KSTR + 4];
            }
            #pragma unroll
            for (int jn = 0; jn < 8; jn++) {
                const uint32_t* Bb = (const uint32_t*)(Vs + (kq + lc) * VSTR + jn * 8 + lr);
                uint32_t bfr[2];
                bfr[0] = Bb[0];
                bfr[1] = Bb[4 * VSTR];
                #pragma unroll
                for (int im = 0; im < 2; im++) mma_tf32(o[im][jn], afr[im], bfr);
            }
        }
        __syncthreads();
    }

    // ycat feeds the Wproj GEMM -> tf32-round at store.
    #pragma unroll
    for (int im = 0; im < 2; im++) {
        #pragma unroll
        for (int hf = 0; hf < 2; hf++) {
            const float inv = 1.0f / l[im][hf];
            const long long row = (long long)b * TSEQ + q0 + wm + im * 16 + hf * 8 + lr;
            #pragma unroll
            for (int jn = 0; jn < 8; jn++) {
                *(float2*)(ycat + row * EDIM + h * HD + jn * 8 + 2 * lc) =
                    make_float2(rnd_tf32(o[im][jn][hf * 2] * inv),
                                rnd_tf32(o[im][jn][hf * 2 + 1] * inv));
            }
        }
    }
}

// ---------------------------------------------------------------------------
// TF32 GEMM: 128x128x16 CTA tile, 8 warps x (64x32), 3-stage cp.async,
// __launch_bounds__(256,2). Raw-bit tf32 fragments (inputs pre-rounded).
// EPI: 1 +bias, 2 +bias,GELU, 3 +bias,+res. RND: tf32-round stores.
// ---------------------------------------------------------------------------
#define GBM 128
#define GBN 128
#define GBK 16
#define ASTR 20     // GBK+4
#define BSTR 136    // GBN+8
#define AS_F (GBM * ASTR)
#define BS_F (GBK * BSTR)
#define G_SMEM_F (3 * (AS_F + BS_F))

template <int EPI, bool RND>
__global__ void __launch_bounds__(256, 2)
mma_gemm(int K,
         const float* __restrict__ A, int lda,
         const float* __restrict__ B, int ldb,
         float* __restrict__ C, int ldc,
         const float* __restrict__ bias,
         const float* __restrict__ res) {
    extern __shared__ float sm[];
    const int m0 = blockIdx.y * GBM;
    const int n0 = blockIdx.x * GBN;
    const int tid  = threadIdx.x;
    const int lane = tid & 31;
    const int warp = tid >> 5;
    const int wm = (warp >> 2) * 64;     // 2 m-warps
    const int wn = (warp & 3) * 32;      // 4 n-warps
    const int lr = lane >> 2;
    const int lc = lane & 3;

    float acc[4][4][4];
    #pragma unroll
    for (int i = 0; i < 4; i++)
        #pragma unroll
        for (int j = 0; j < 4; j++)
            #pragma unroll
            for (int q = 0; q < 4; q++) acc[i][j][q] = 0.0f;

    const int KT = K / GBK;

    auto load_tile = [&](int kt, int st) {
        float* As = sm + st * AS_F;
        float* Bs = sm + 3 * AS_F + st * BS_F;
        const int k0 = kt * GBK;
        #pragma unroll
        for (int i = tid; i < GBM * GBK / 4; i += 256) {
            int r = i >> 2, kc = (i & 3) << 2;
            cp_async16(As + r * ASTR + kc, A + (long long)(m0 + r) * lda + k0 + kc);
        }
        #pragma unroll
        for (int i = tid; i < GBK * GBN / 4; i += 256) {
            int r = i >> 5, nc = (i & 31) << 2;
            cp_async16(Bs + r * BSTR + nc, B + (long long)(k0 + r) * ldb + n0 + nc);
        }
        cp_commit();
    };

    load_tile(0, 0);
    load_tile(1, 1);

    int st = 0;
    for (int kt = 0; kt < KT; kt++) {
        cp_wait<1>();
        __syncthreads();
        if (kt + 2 < KT) {
            int st2 = st + 2; if (st2 >= 3) st2 -= 3;
            load_tile(kt + 2, st2);
        }
        const float* As = sm + st * AS_F;
        const float* Bs = sm + 3 * AS_F + st * BS_F;

        #pragma unroll
        for (int kq = 0; kq < GBK; kq += 8) {
            uint32_t afr[4][4];
            #pragma unroll
            for (int im = 0; im < 4; im++) {
                const uint32_t* Ab = (const uint32_t*)(As + (wm + im * 16 + lr) * ASTR + kq + lc);
                afr[im][0] = Ab[0];
                afr[im][1] = Ab[8 * ASTR];
                afr[im][2] = Ab[4];
                afr[im][3] = Ab[8 * ASTR + 4];
            }
            #pragma unroll
            for (int jn = 0; jn < 4; jn++) {
                const uint32_t* Bb = (const uint32_t*)(Bs + (kq + lc) * BSTR + wn + jn * 8 + lr);
                uint32_t bfr[2];
                bfr[0] = Bb[0];
                bfr[1] = Bb[4 * BSTR];
                #pragma unroll
                for (int im = 0; im < 4; im++) mma_tf32(acc[im][jn], afr[im], bfr);
            }
        }
        __syncthreads();
        if (++st == 3) st = 0;
    }

    #pragma unroll
    for (int im = 0; im < 4; im++) {
        const int r0 = m0 + wm + im * 16 + lr;
        #pragma unroll
        for (int jn = 0; jn < 4; jn++) {
            const int cb = n0 + wn + jn * 8 + lc * 2;
            float bv0 = bias[cb], bv1 = bias[cb + 1];
            #pragma unroll
            for (int hf = 0; hf < 2; hf++) {
                const int r = r0 + hf * 8;
                float v0 = acc[im][jn][hf * 2]     + bv0;
                float v1 = acc[im][jn][hf * 2 + 1] + bv1;
                if (EPI == 2) { v0 = gelu_tanh(v0); v1 = gelu_tanh(v1); }
                if (EPI == 3) {
                    const float* rp = res + (long long)r * ldc + cb;
                    v0 += rp[0]; v1 += rp[1];
                }
                if (RND) { v0 = rnd_tf32(v0); v1 = rnd_tf32(v1); }
                float* cp = C + (long long)r * ldc + cb;
                cp[0] = v0; cp[1] = v1;
            }
        }
    }
}

// ---------------------------------------------------------------------------
extern "C" void kernel_launch(void* const* d_in, const int* in_sizes, int n_in,
                              void* d_out, int out_size) {
    const float* x     = (const float*)d_in[0];
    const float* ln1g  = (const float*)d_in[1];
    const float* ln1b  = (const float*)d_in[2];
    const float* Wqkv  = (const float*)d_in[3];
    const float* bqkv  = (const float*)d_in[4];
    const float* Wproj = (const float*)d_in[5];
    const float* bproj = (const float*)d_in[6];
    const float* ln2g  = (const float*)d_in[7];
    const float* ln2b  = (const float*)d_in[8];
    const float* Wfc   = (const float*)d_in[9];
    const float* bfc   = (const float*)d_in[10];
    const float* Wout  = (const float*)d_in[11];
    const float* bout  = (const float*)d_in[12];
    float* out = (float*)d_out;

    float *xn, *qkv, *ycat, *hbuf, *wr;
    cudaGetSymbolAddress((void**)&xn,   g_xn);
    cudaGetSymbolAddress((void**)&qkv,  g_qkv);
    cudaGetSymbolAddress((void**)&ycat, g_ycat);
    cudaGetSymbolAddress((void**)&hbuf, g_h);
    cudaGetSymbolAddress((void**)&wr,   g_wr);

    const int gsmem = G_SMEM_F * sizeof(float);   // ~55.7 KB
    const int fsmem = FL_SMEM_F * sizeof(float);  // ~206 KB
    static bool attr_done = false;
    if (!attr_done) {
        cudaFuncSetAttribute(mma_gemm<1,true >, cudaFuncAttributeMaxDynamicSharedMemorySize, gsmem);
        cudaFuncSetAttribute(mma_gemm<2,true >, cudaFuncAttributeMaxDynamicSharedMemorySize, gsmem);
        cudaFuncSetAttribute(mma_gemm<3,false>, cudaFuncAttributeMaxDynamicSharedMemorySize, gsmem);
        cudaFuncSetAttribute(flash_kernel, cudaFuncAttributeMaxDynamicSharedMemorySize, fsmem);
        attr_done = true;
    }

    // 0) round weights to tf32 (idempotent)
    round_w_kernel<<<(3145728/4 + 255)/256, 256>>>(Wqkv,  wr + WR_QKV,  3145728/4);
    round_w_kernel<<<(1048576/4 + 255)/256, 256>>>(Wproj, wr + WR_PROJ, 1048576/4);
    round_w_kernel<<<(4194304/4 + 255)/256, 256>>>(Wfc,   wr + WR_FC,   4194304/4);
    round_w_kernel<<<(4194304/4 + 255)/256, 256>>>(Wout,  wr + WR_OUT,  4194304/4);

    // 1) LN1 (tf32-rounded out)
    ln_kernel<<<RROWS, 256>>>(x, ln1g, ln1b, xn);

    // 2) QKV = LN1(x) @ Wqkv + bqkv  (rounded; feeds flash)
    mma_gemm<1,true><<<dim3(3 * EDIM / GBN, RROWS / GBM), 256, gsmem>>>(
        EDIM, xn, EDIM, wr + WR_QKV, 3 * EDIM, qkv, 3 * EDIM, bqkv, nullptr);

    // 3) flash attention -> ycat (rounded); 256 q-rows per CTA
    flash_kernel<<<dim3(TSEQ / 256, HEADS, BATCH), 256, fsmem>>>(qkv, ycat);

    // 4) x1 = x + ycat @ Wproj + bproj -> d_out (full fp32)
    mma_gemm<3,false><<<dim3(EDIM / GBN, RROWS / GBM), 256, gsmem>>>(
        EDIM, ycat, EDIM, wr + WR_PROJ, EDIM, out, EDIM, bproj, x);

    // 5) LN2(x1) -> xn (rounded)
    ln_kernel<<<RROWS, 256>>>(out, ln2g, ln2b, xn);

    // 6) h = gelu(xn @ Wfc + bfc) (rounded; feeds Wout GEMM)
    mma_gemm<2,true><<<dim3(HID / GBN, RROWS / GBM), 256, gsmem>>>(
        EDIM, xn, EDIM, wr + WR_FC, HID, hbuf, HID, bfc, nullptr);

    // 7) out = x1 + h @ Wout + bout (full fp32)
    mma_gemm<3,false><<<dim3(EDIM / GBN, RROWS / GBM), 256, gsmem>>>(
        HID, hbuf, HID, wr + WR_OUT, EDIM, out, EDIM, bout, out);
}

// round 12
// speedup vs baseline: 2.5806x; 1.6952x over previous
#include <cuda_runtime.h>
#include <cuda_fp16.h>
#include <cstdint>

// ---------------------------------------------------------------------------
// TransformerBlock B=8,T=1024,E=1024,H=16,HD=64,HID=4096 fp32.
// R11: all MMAs moved tf32->fp16 m16n8k16 (same 10-bit mantissa, 2x rate,
// half the fragment traffic). Activations stored fp16; weights transposed
// to [N][K] fp16 once. Flash uses ldmatrix.trans for V. Residual/output
// math stays fp32.
// ---------------------------------------------------------------------------

#define RROWS 8192
#define EDIM  1024
#define HEADS 16
#define HD    64
#define HID   4096
#define TSEQ  1024
#define BATCH 8

__device__ __half g_xn  [RROWS * EDIM];
__device__ __half g_qkv [RROWS * 3 * EDIM];
__device__ __half g_ycat[RROWS * EDIM];
__device__ __half g_h   [RROWS * HID];
__device__ __half g_wh  [12582912];   // transposed fp16 weights

#define WR_QKV  0            // [3072][1024]
#define WR_PROJ 3145728      // [1024][1024]
#define WR_FC   4194304      // [4096][1024]
#define WR_OUT  8388608      // [1024][4096]

__device__ __forceinline__ float gelu_tanh(float x) {
    float x3 = x * x * x;
    return 0.5f * x * (1.0f + tanhf(0.7978845608028654f * (x + 0.044715f * x3)));
}
__device__ __forceinline__ void cp_async16(void* smem_dst, const void* gsrc) {
    uint32_t d = (uint32_t)__cvta_generic_to_shared(smem_dst);
    asm volatile("cp.async.cg.shared.global [%0], [%1], 16;\n" :: "r"(d), "l"(gsrc));
}
__device__ __forceinline__ void cp_commit() { asm volatile("cp.async.commit_group;\n"); }
template <int N>
__device__ __forceinline__ void cp_wait() { asm volatile("cp.async.wait_group %0;\n" :: "n"(N)); }

// m16n8k16 fp16 MMA, fp32 accumulate.
__device__ __forceinline__ void mma_f16(float* c, const uint32_t* a, const uint32_t* b) {
    asm volatile(
        "mma.sync.aligned.m16n8k16.row.col.f32.f16.f16.f32 "
        "{%0,%1,%2,%3}, {%4,%5,%6,%7}, {%8,%9}, {%0,%1,%2,%3};"
        : "+f"(c[0]), "+f"(c[1]), "+f"(c[2]), "+f"(c[3])
        : "r"(a[0]), "r"(a[1]), "r"(a[2]), "r"(a[3]), "r"(b[0]), "r"(b[1]));
}

__device__ __forceinline__ void ldmatrix_x2_trans(uint32_t& r0, uint32_t& r1, uint32_t saddr) {
    asm volatile("ldmatrix.sync.aligned.m8n8.x2.trans.shared.b16 {%0,%1}, [%2];"
                 : "=r"(r0), "=r"(r1) : "r"(saddr));
}

// ---------------------------------------------------------------------------
// Weight transpose + fp16 convert:  WT[n][k] = half(W[k][n]).  in: [K][N].
// ---------------------------------------------------------------------------
__global__ void transpose_half(const float* __restrict__ in, __half* __restrict__ outp,
                               int K, int N) {
    __shared__ float t[32][33];
    const int n0 = blockIdx.x * 32, k0 = blockIdx.y * 32;
    const int tx = threadIdx.x, ty = threadIdx.y;
    #pragma unroll
    for (int j = 0; j < 32; j += 8)
        t[ty + j][tx] = in[(long long)(k0 + ty + j) * N + n0 + tx];
    __syncthreads();
    #pragma unroll
    for (int j = 0; j < 32; j += 8)
        outp[(long long)(n0 + ty + j) * K + k0 + tx] = __float2half(t[tx][ty + j]);
}

// ---------------------------------------------------------------------------
// LayerNorm: one block (256 threads) per 1024-col row; fp32 in, fp16 out.
// ---------------------------------------------------------------------------
__global__ void ln_kernel(const float* __restrict__ x,
                          const float* __restrict__ g,
                          const float* __restrict__ b,
                          __half* __restrict__ out) {
    __shared__ float red[8];
    const long long row = blockIdx.x;
    const int t = threadIdx.x;
    float4 v = ((const float4*)(x + row * EDIM))[t];

    float s = v.x + v.y + v.z + v.w;
    #pragma unroll
    for (int o = 16; o; o >>= 1) s += __shfl_xor_sync(~0u, s, o);
    if ((t & 31) == 0) red[t >> 5] = s;
    __syncthreads();
    if (t < 8) {
        s = red[t];
        #pragma unroll
        for (int o = 4; o; o >>= 1) s += __shfl_xor_sync(0xffu, s, o);
        if (t == 0) red[0] = s;
    }
    __syncthreads();
    const float mean = red[0] * (1.0f / EDIM);

    float dx = v.x - mean, dy = v.y - mean, dz = v.z - mean, dw = v.w - mean;
    float q = dx * dx + dy * dy + dz * dz + dw * dw;
    #pragma unroll
    for (int o = 16; o; o >>= 1) q += __shfl_xor_sync(~0u, q, o);
    __syncthreads();
    if ((t & 31) == 0) red[t >> 5] = q;
    __syncthreads();
    if (t < 8) {
        q = red[t];
        #pragma unroll
        for (int o = 4; o; o >>= 1) q += __shfl_xor_sync(0xffu, q, o);
        if (t == 0) red[0] = q;
    }
    __syncthreads();
    const float rstd = rsqrtf(red[0] * (1.0f / EDIM) + 1e-5f);

    const float4 gg = ((const float4*)g)[t];
    const float4 bb = ((const float4*)b)[t];
    half2 h0 = __floats2half2_rn(dx * rstd * gg.x + bb.x, dy * rstd * gg.y + bb.y);
    half2 h1 = __floats2half2_rn(dz * rstd * gg.z + bb.z, dw * rstd * gg.w + bb.w);
    half2* op = (half2*)(out + row * EDIM + t * 4);
    op[0] = h0; op[1] = h1;
}

// ---------------------------------------------------------------------------
// Flash attention fp16, non-causal. CTA = 256 q-rows of one (b,h), 8 warps
// (warp w owns rows [32w,32w+32)). Key tiles of 64, double-buffered cp.async.
// Q/K/V/P in fp16 smem; S/O accumulate fp32. V consumed via ldmatrix.trans.
// ---------------------------------------------------------------------------
#define QSTR 72   // halves per row (64 + 8 pad)
#define FL_QOFF 0
#define FL_KOFF (256 * QSTR)
#define FL_VOFF (FL_KOFF + 2 * 64 * QSTR)
#define FL_POFF (FL_VOFF + 2 * 64 * QSTR)
#define FL_SMEM_H (FL_POFF + 256 * QSTR)

__global__ void __launch_bounds__(256)
flash_kernel(const __half* __restrict__ qkv, __half* __restrict__ ycat) {
    extern __shared__ __half sh[];
    __half* Qsm = sh + FL_QOFF;
    __half* Psm = sh + FL_POFF;

    const int tid  = threadIdx.x;
    const int lane = tid & 31;
    const int warp = tid >> 5;
    const int lr = lane >> 2;
    const int lc = lane & 3;
    const int q0 = blockIdx.x * 256;
    const int h  = blockIdx.y;
    const int b  = blockIdx.z;
    const int wm = warp * 32;

    const __half* qkvb = qkv + (long long)b * TSEQ * 3 * EDIM;
    const __half* Qg = qkvb + h * HD;
    const __half* Kg = qkvb + EDIM + h * HD;
    const __half* Vg = qkvb + 2 * EDIM + h * HD;

    // Q tile (scaled by 0.125 — exact exponent shift in fp16)
    const half2 qsc = __floats2half2_rn(0.125f, 0.125f);
    #pragma unroll
    for (int i = tid; i < 256 * 8; i += 256) {
        int r = i >> 3, ch = (i & 7) << 3;     // 8 halves per chunk
        uint4 v = *(const uint4*)(Qg + (long long)(q0 + r) * 3 * EDIM + ch);
        half2* hv = (half2*)&v;
        hv[0] = __hmul2(hv[0], qsc); hv[1] = __hmul2(hv[1], qsc);
        hv[2] = __hmul2(hv[2], qsc); hv[3] = __hmul2(hv[3], qsc);
        *(uint4*)(Qsm + r * QSTR + ch) = v;
    }

    auto load_kv = [&](int j, int buf) {
        __half* Ks = sh + FL_KOFF + buf * 64 * QSTR;
        __half* Vs = sh + FL_VOFF + buf * 64 * QSTR;
        const __half* Kj = Kg + (long long)(j * 64) * 3 * EDIM;
        const __half* Vj = Vg + (long long)(j * 64) * 3 * EDIM;
        #pragma unroll
        for (int i = tid; i < 64 * 8; i += 256) {
            int r = i >> 3, ch = (i & 7) << 3;
            cp_async16(Ks + r * QSTR + ch, Kj + (long long)r * 3 * EDIM + ch);
            cp_async16(Vs + r * QSTR + ch, Vj + (long long)r * 3 * EDIM + ch);
        }
        cp_commit();
    };

    float o[2][8][4];
    float m[2][2], l[2][2];
    #pragma unroll
    for (int im = 0; im < 2; im++) {
        #pragma unroll
        for (int jn = 0; jn < 8; jn++)
            #pragma unroll
            for (int q = 0; q < 4; q++) o[im][jn][q] = 0.0f;
        m[im][0] = m[im][1] = -1e30f;
        l[im][0] = l[im][1] = 0.0f;
    }

    load_kv(0, 0);

    const int NT = TSEQ / 64;
    for (int j = 0; j < NT; j++) {
        const int buf = j & 1;
        if (j + 1 < NT) { load_kv(j + 1, buf ^ 1); cp_wait<1>(); }
        else           { cp_wait<0>(); }
        __syncthreads();

        const __half* Ks = sh + FL_KOFF + buf * 64 * QSTR;
        const __half* Vs = sh + FL_VOFF + buf * 64 * QSTR;

        // ---- S = Q K^T  (k = d, 4 ksteps of 16) ----
        float s[2][8][4];
        #pragma unroll
        for (int im = 0; im < 2; im++)
            #pragma unroll
            for (int jn = 0; jn < 8; jn++)
                #pragma unroll
                for (int q = 0; q < 4; q++) s[im][jn][q] = 0.0f;

        #pragma unroll
        for (int kq = 0; kq < HD; kq += 16) {
            uint32_t afr[2][4];
            #pragma unroll
            for (int im = 0; im < 2; im++) {
                const __half* Ab = Qsm + (wm + im * 16 + lr) * QSTR + kq + lc * 2;
                afr[im][0] = *(const uint32_t*)(Ab);
                afr[im][1] = *(const uint32_t*)(Ab + 8 * QSTR);
                afr[im][2] = *(const uint32_t*)(Ab + 8);
                afr[im][3] = *(const uint32_t*)(Ab + 8 * QSTR + 8);
            }
            #pragma unroll
            for (int jn = 0; jn < 8; jn++) {
                const __half* Bb = Ks + (jn * 8 + lr) * QSTR + kq + lc * 2;
                uint32_t bfr[2];
                bfr[0] = *(const uint32_t*)(Bb);
                bfr[1] = *(const uint32_t*)(Bb + 8);
                #pragma unroll
                for (int im = 0; im < 2; im++) mma_f16(s[im][jn], afr[im], bfr);
            }
        }

        // ---- online softmax; write fp16 P (own rows) ----
        #pragma unroll
        for (int im = 0; im < 2; im++) {
            #pragma unroll
            for (int hf = 0; hf < 2; hf++) {
                float mx = -1e30f;
                #pragma unroll
                for (int jn = 0; jn < 8; jn++)
                    mx = fmaxf(mx, fmaxf(s[im][jn][hf * 2], s[im][jn][hf * 2 + 1]));
                mx = fmaxf(mx, __shfl_xor_sync(~0u, mx, 1));
                mx = fmaxf(mx, __shfl_xor_sync(~0u, mx, 2));
                const float mnew = fmaxf(m[im][hf], mx);
                const float alpha = __expf(m[im][hf] - mnew);
                m[im][hf] = mnew;
                const int prow = wm + im * 16 + hf * 8 + lr;
                float sum = 0.0f;
                #pragma unroll
                for (int jn = 0; jn < 8; jn++) {
                    float p0 = __expf(s[im][jn][hf * 2]     - mnew);
                    float p1 = __expf(s[im][jn][hf * 2 + 1] - mnew);
                    sum += p0 + p1;
                    *(half2*)(Psm + prow * QSTR + jn * 8 + 2 * lc) = __floats2half2_rn(p0, p1);
                }
                sum += __shfl_xor_sync(~0u, sum, 1);
                sum += __shfl_xor_sync(~0u, sum, 2);
                l[im][hf] = l[im][hf] * alpha + sum;
                #pragma unroll
                for (int jn = 0; jn < 8; jn++) {
                    o[im][jn][hf * 2]     *= alpha;
                    o[im][jn][hf * 2 + 1] *= alpha;
                }
            }
        }
        __syncwarp();

        // ---- O += P @ V  (k = keys, 4 ksteps of 16; V via ldmatrix.trans) ----
        #pragma unroll
        for (int kq = 0; kq < 64; kq += 16) {
            uint32_t afr[2][4];
            #pragma unroll
            for (int im = 0; im < 2; im++) {
                const __half* Ab = Psm + (wm + im * 16 + lr) * QSTR + kq + lc * 2;
                afr[im][0] = *(const uint32_t*)(Ab);
                afr[im][1] = *(const uint32_t*)(Ab + 8 * QSTR);
                afr[im][2] = *(const uint32_t*)(Ab + 8);
                afr[im][3] = *(const uint32_t*)(Ab + 8 * QSTR + 8);
            }
            #pragma unroll
            for (int jn = 0; jn < 8; jn++) {
                uint32_t bfr[2];
                uint32_t saddr = (uint32_t)__cvta_generic_to_shared(
                    Vs + (kq + (lane & 15)) * QSTR + jn * 8);
                ldmatrix_x2_trans(bfr[0], bfr[1], saddr);
                #pragma unroll
                for (int im = 0; im < 2; im++) mma_f16(o[im][jn], afr[im], bfr);
            }
        }
        __syncthreads();
    }

    // ycat (fp16; feeds Wproj GEMM)
    #pragma unroll
    for (int im = 0; im < 2; im++) {
        #pragma unroll
        for (int hf = 0; hf < 2; hf++) {
            const float inv = 1.0f / l[im][hf];
            const long long row = (long long)b * TSEQ + q0 + wm + im * 16 + hf * 8 + lr;
            #pragma unroll
            for (int jn = 0; jn < 8; jn++) {
                *(half2*)(ycat + row * EDIM + h * HD + jn * 8 + 2 * lc) =
                    __floats2half2_rn(o[im][jn][hf * 2] * inv, o[im][jn][hf * 2 + 1] * inv);
            }
        }
    }
}

// ---------------------------------------------------------------------------
// fp16 GEMM: 128x128x32 CTA tile, 8 warps x (64x32), 3-stage cp.async,
// __launch_bounds__(256,2). A[m][k] fp16, BT[n][k] fp16 (K-contiguous).
// EPI: 1 +bias, 2 +bias,GELU, 3 +bias,+res(fp32). HOUT: fp16 C, else fp32.
// ---------------------------------------------------------------------------
#define GBM 128
#define GBN 128
#define GBK 32
#define GSTR 40               // halves per smem row (32 + 8 pad)
#define TILE_H (128 * GSTR)   // per-operand per-stage halves
#define G_SMEM_B (3 * 2 * TILE_H * 2)

template <int EPI, bool HOUT>
__global__ void __launch_bounds__(256, 2)
mma_gemm(int K,
         const __half* __restrict__ A, int lda,
         const __half* __restrict__ BT, int ldb,
         void* __restrict__ Cv, int ldc,
         const float* __restrict__ bias,
         const float* __restrict__ res) {
    extern __shared__ __half gsh[];
    const int m0 = blockIdx.y * GBM;
    const int n0 = blockIdx.x * GBN;
    const int tid  = threadIdx.x;
    const int lane = tid & 31;
    const int warp = tid >> 5;
    const int wm = (warp >> 2) * 64;     // 2 m-warps
    const int wn = (warp & 3) * 32;      // 4 n-warps
    const int lr = lane >> 2;
    const int lc = lane & 3;

    float acc[4][4][4];
    #pragma unroll
    for (int i = 0; i < 4; i++)
        #pragma unroll
        for (int j = 0; j < 4; j++)
            #pragma unroll
            for (int q = 0; q < 4; q++) acc[i][j][q] = 0.0f;

    const int KT = K / GBK;

    auto load_tile = [&](int kt, int st) {
        __half* As = gsh + st * 2 * TILE_H;
        __half* Bs = gsh + st * 2 * TILE_H + TILE_H;
        const int k0 = kt * GBK;
        // 128 rows x 32 halves = 4 chunks of 16B per row, each operand
        #pragma unroll
        for (int i = tid; i < 512; i += 256) {
            int r = i >> 2, ch = (i & 3) << 3;
            cp_async16(As + r * GSTR + ch, A  + (long long)(m0 + r) * lda + k0 + ch);
        }
        #pragma unroll
        for (int i = tid; i < 512; i += 256) {
            int r = i >> 2, ch = (i & 3) << 3;
            cp_async16(Bs + r * GSTR + ch, BT + (long long)(n0 + r) * ldb + k0 + ch);
        }
        cp_commit();
    };

    load_tile(0, 0);
    load_tile(1, 1);

    int st = 0;
    for (int kt = 0; kt < KT; kt++) {
        cp_wait<1>();
        __syncthreads();
        if (kt + 2 < KT) {
            int st2 = st + 2; if (st2 >= 3) st2 -= 3;
            load_tile(kt + 2, st2);
        }
        const __half* As = gsh + st * 2 * TILE_H;
        const __half* Bs = gsh + st * 2 * TILE_H + TILE_H;

        #pragma unroll
        for (int kq = 0; kq < GBK; kq += 16) {
            uint32_t afr[4][4];
            #pragma unroll
            for (int im = 0; im < 4; im++) {
                const __half* Ab = As + (wm + im * 16 + lr) * GSTR + kq + lc * 2;
                afr[im][0] = *(const uint32_t*)(Ab);
                afr[im][1] = *(const uint32_t*)(Ab + 8 * GSTR);
                afr[im][2] = *(const uint32_t*)(Ab + 8);
                afr[im][3] = *(const uint32_t*)(Ab + 8 * GSTR + 8);
            }
            #pragma unroll
            for (int jn = 0; jn < 4; jn++) {
                const __half* Bb = Bs + (wn + jn * 8 + lr) * GSTR + kq + lc * 2;
                uint32_t bfr[2];
                bfr[0] = *(const uint32_t*)(Bb);
                bfr[1] = *(const uint32_t*)(Bb + 8);
                #pragma unroll
                for (int im = 0; im < 4; im++) mma_f16(acc[im][jn], afr[im], bfr);
            }
        }
        __syncthreads();
        if (++st == 3) st = 0;
    }

    #pragma unroll
    for (int im = 0; im < 4; im++) {
        const int r0 = m0 + wm + im * 16 + lr;
        #pragma unroll
        for (int jn = 0; jn < 4; jn++) {
            const int cb = n0 + wn + jn * 8 + lc * 2;
            float bv0 = bias[cb], bv1 = bias[cb + 1];
            #pragma unroll
            for (int hf = 0; hf < 2; hf++) {
                const int r = r0 + hf * 8;
                float v0 = acc[im][jn][hf * 2]     + bv0;
                float v1 = acc[im][jn][hf * 2 + 1] + bv1;
                if (EPI == 2) { v0 = gelu_tanh(v0); v1 = gelu_tanh(v1); }
                if (EPI == 3) {
                    const float* rp = res + (long long)r * ldc + cb;
                    v0 += rp[0]; v1 += rp[1];
                }
                if (HOUT) {
                    *(half2*)((__half*)Cv + (long long)r * ldc + cb) =
                        __floats2half2_rn(v0, v1);
                } else {
                    float* cp = (float*)Cv + (long long)r * ldc + cb;
                    cp[0] = v0; cp[1] = v1;
                }
            }
        }
    }
}

// ---------------------------------------------------------------------------
extern "C" void kernel_launch(void* const* d_in, const int* in_sizes, int n_in,
                              void* d_out, int out_size) {
    const float* x     = (const float*)d_in[0];
    const float* ln1g  = (const float*)d_in[1];
    const float* ln1b  = (const float*)d_in[2];
    const float* Wqkv  = (const float*)d_in[3];
    const float* bqkv  = (const float*)d_in[4];
    const float* Wproj = (const float*)d_in[5];
    const float* bproj = (const float*)d_in[6];
    const float* ln2g  = (const float*)d_in[7];
    const float* ln2b  = (const float*)d_in[8];
    const float* Wfc   = (const float*)d_in[9];
    const float* bfc   = (const float*)d_in[10];
    const float* Wout  = (const float*)d_in[11];
    const float* bout  = (const float*)d_in[12];
    float* out = (float*)d_out;

    __half *xn, *qkv, *ycat, *hbuf, *wh;
    cudaGetSymbolAddress((void**)&xn,   g_xn);
    cudaGetSymbolAddress((void**)&qkv,  g_qkv);
    cudaGetSymbolAddress((void**)&ycat, g_ycat);
    cudaGetSymbolAddress((void**)&hbuf, g_h);
    cudaGetSymbolAddress((void**)&wh,   g_wh);

    const int gsmem = G_SMEM_B;                    // 61440 B
    const int fsmem = FL_SMEM_H * sizeof(__half);  // 110592 B
    static bool attr_done = false;
    if (!attr_done) {
        cudaFuncSetAttribute(mma_gemm<1,true >, cudaFuncAttributeMaxDynamicSharedMemorySize, gsmem);
        cudaFuncSetAttribute(mma_gemm<2,true >, cudaFuncAttributeMaxDynamicSharedMemorySize, gsmem);
        cudaFuncSetAttribute(mma_gemm<3,false>, cudaFuncAttributeMaxDynamicSharedMemorySize, gsmem);
        cudaFuncSetAttribute(flash_kernel, cudaFuncAttributeMaxDynamicSharedMemorySize, fsmem);
        attr_done = true;
    }

    // 0) transpose + fp16-convert weights: WT[n][k]
    transpose_half<<<dim3(3 * EDIM / 32, EDIM / 32), dim3(32, 8)>>>(Wqkv,  wh + WR_QKV,  EDIM, 3 * EDIM);
    transpose_half<<<dim3(EDIM / 32,     EDIM / 32), dim3(32, 8)>>>(Wproj, wh + WR_PROJ, EDIM, EDIM);
    transpose_half<<<dim3(HID / 32,      EDIM / 32), dim3(32, 8)>>>(Wfc,   wh + WR_FC,   EDIM, HID);
    transpose_half<<<dim3(EDIM / 32,     HID / 32),  dim3(32, 8)>>>(Wout,  wh + WR_OUT,  HID,  EDIM);

    // 1) LN1 -> fp16
    ln_kernel<<<RROWS, 256>>>(x, ln1g, ln1b, xn);

    // 2) QKV = LN1(x) @ Wqkv + bqkv  (fp16 out; feeds flash)
    mma_gemm<1,true><<<dim3(3 * EDIM / GBN, RROWS / GBM), 256, gsmem>>>(
        EDIM, xn, EDIM, wh + WR_QKV, EDIM, qkv, 3 * EDIM, bqkv, nullptr);

    // 3) flash attention -> ycat (fp16)
    flash_kernel<<<dim3(TSEQ / 256, HEADS, BATCH), 256, fsmem>>>(qkv, ycat);

    // 4) x1 = x + ycat @ Wproj + bproj -> d_out (fp32)
    mma_gemm<3,false><<<dim3(EDIM / GBN, RROWS / GBM), 256, gsmem>>>(
        EDIM, ycat, EDIM, wh + WR_PROJ, EDIM, out, EDIM, bproj, x);

    // 5) LN2(x1) -> fp16
    ln_kernel<<<RROWS, 256>>>(out, ln2g, ln2b, xn);

    // 6) h = gelu(xn @ Wfc + bfc)  (fp16 out)
    mma_gemm<2,true><<<dim3(HID / GBN, RROWS / GBM), 256, gsmem>>>(
        EDIM, xn, EDIM, wh + WR_FC, EDIM, hbuf, HID, bfc, nullptr);

    // 7) out = x1 + h @ Wout + bout (fp32)
    mma_gemm<3,false><<<dim3(EDIM / GBN, RROWS / GBM), 256, gsmem>>>(
        HID, hbuf, HID, wh + WR_OUT, HID, out, EDIM, bout, out);
}

// round 13
// speedup vs baseline: 2.7247x; 1.0559x over previous
#include <cuda_runtime.h>
#include <cuda_fp16.h>
#include <cstdint>

// ---------------------------------------------------------------------------
// TransformerBlock B=8,T=1024,E=1024,H=16,HD=64,HID=4096 fp32.
// R12: R11 (fp16 m16n8k16 everywhere) + ldmatrix fragment loads in all MMA
// inner loops (A via x4, B via x2) and Q-fragment hoisting in flash.
// ---------------------------------------------------------------------------

#define RROWS 8192
#define EDIM  1024
#define HEADS 16
#define HD    64
#define HID   4096
#define TSEQ  1024
#define BATCH 8

__device__ __half g_xn  [RROWS * EDIM];
__device__ __half g_qkv [RROWS * 3 * EDIM];
__device__ __half g_ycat[RROWS * EDIM];
__device__ __half g_h   [RROWS * HID];
__device__ __half g_wh  [12582912];   // transposed fp16 weights

#define WR_QKV  0            // [3072][1024]
#define WR_PROJ 3145728      // [1024][1024]
#define WR_FC   4194304      // [4096][1024]
#define WR_OUT  8388608      // [1024][4096]

__device__ __forceinline__ float gelu_tanh(float x) {
    float x3 = x * x * x;
    return 0.5f * x * (1.0f + tanhf(0.7978845608028654f * (x + 0.044715f * x3)));
}
__device__ __forceinline__ void cp_async16(void* smem_dst, const void* gsrc) {
    uint32_t d = (uint32_t)__cvta_generic_to_shared(smem_dst);
    asm volatile("cp.async.cg.shared.global [%0], [%1], 16;\n" :: "r"(d), "l"(gsrc));
}
__device__ __forceinline__ void cp_commit() { asm volatile("cp.async.commit_group;\n"); }
template <int N>
__device__ __forceinline__ void cp_wait() { asm volatile("cp.async.wait_group %0;\n" :: "n"(N)); }

// m16n8k16 fp16 MMA, fp32 accumulate.
__device__ __forceinline__ void mma_f16(float* c, const uint32_t* a, const uint32_t* b) {
    asm volatile(
        "mma.sync.aligned.m16n8k16.row.col.f32.f16.f16.f32 "
        "{%0,%1,%2,%3}, {%4,%5,%6,%7}, {%8,%9}, {%0,%1,%2,%3};"
        : "+f"(c[0]), "+f"(c[1]), "+f"(c[2]), "+f"(c[3])
        : "r"(a[0]), "r"(a[1]), "r"(a[2]), "r"(a[3]), "r"(b[0]), "r"(b[1]));
}

__device__ __forceinline__ void ldmatrix_x4(uint32_t& r0, uint32_t& r1, uint32_t& r2,
                                            uint32_t& r3, uint32_t saddr) {
    asm volatile("ldmatrix.sync.aligned.m8n8.x4.shared.b16 {%0,%1,%2,%3}, [%4];"
                 : "=r"(r0), "=r"(r1), "=r"(r2), "=r"(r3) : "r"(saddr));
}
__device__ __forceinline__ void ldmatrix_x2(uint32_t& r0, uint32_t& r1, uint32_t saddr) {
    asm volatile("ldmatrix.sync.aligned.m8n8.x2.shared.b16 {%0,%1}, [%2];"
                 : "=r"(r0), "=r"(r1) : "r"(saddr));
}
__device__ __forceinline__ void ldmatrix_x2_trans(uint32_t& r0, uint32_t& r1, uint32_t saddr) {
    asm volatile("ldmatrix.sync.aligned.m8n8.x2.trans.shared.b16 {%0,%1}, [%2];"
                 : "=r"(r0), "=r"(r1) : "r"(saddr));
}

// ---------------------------------------------------------------------------
// Weight transpose + fp16 convert:  WT[n][k] = half(W[k][n]).  in: [K][N].
// ---------------------------------------------------------------------------
__global__ void transpose_half(const float* __restrict__ in, __half* __restrict__ outp,
                               int K, int N) {
    __shared__ float t[32][33];
    const int n0 = blockIdx.x * 32, k0 = blockIdx.y * 32;
    const int tx = threadIdx.x, ty = threadIdx.y;
    #pragma unroll
    for (int j = 0; j < 32; j += 8)
        t[ty + j][tx] = in[(long long)(k0 + ty + j) * N + n0 + tx];
    __syncthreads();
    #pragma unroll
    for (int j = 0; j < 32; j += 8)
        outp[(long long)(n0 + ty + j) * K + k0 + tx] = __float2half(t[tx][ty + j]);
}

// ---------------------------------------------------------------------------
// LayerNorm: one block (256 threads) per 1024-col row; fp32 in, fp16 out.
// ---------------------------------------------------------------------------
__global__ void ln_kernel(const float* __restrict__ x,
                          const float* __restrict__ g,
                          const float* __restrict__ b,
                          __half* __restrict__ out) {
    __shared__ float red[8];
    const long long row = blockIdx.x;
    const int t = threadIdx.x;
    float4 v = ((const float4*)(x + row * EDIM))[t];

    float s = v.x + v.y + v.z + v.w;
    #pragma unroll
    for (int o = 16; o; o >>= 1) s += __shfl_xor_sync(~0u, s, o);
    if ((t & 31) == 0) red[t >> 5] = s;
    __syncthreads();
    if (t < 8) {
        s = red[t];
        #pragma unroll
        for (int o = 4; o; o >>= 1) s += __shfl_xor_sync(0xffu, s, o);
        if (t == 0) red[0] = s;
    }
    __syncthreads();
    const float mean = red[0] * (1.0f / EDIM);

    float dx = v.x - mean, dy = v.y - mean, dz = v.z - mean, dw = v.w - mean;
    float q = dx * dx + dy * dy + dz * dz + dw * dw;
    #pragma unroll
    for (int o = 16; o; o >>= 1) q += __shfl_xor_sync(~0u, q, o);
    __syncthreads();
    if ((t & 31) == 0) red[t >> 5] = q;
    __syncthreads();
    if (t < 8) {
        q = red[t];
        #pragma unroll
        for (int o = 4; o; o >>= 1) q += __shfl_xor_sync(0xffu, q, o);
        if (t == 0) red[0] = q;
    }
    __syncthreads();
    const float rstd = rsqrtf(red[0] * (1.0f / EDIM) + 1e-5f);

    const float4 gg = ((const float4*)g)[t];
    const float4 bb = ((const float4*)b)[t];
    half2 h0 = __floats2half2_rn(dx * rstd * gg.x + bb.x, dy * rstd * gg.y + bb.y);
    half2 h1 = __floats2half2_rn(dz * rstd * gg.z + bb.z, dw * rstd * gg.w + bb.w);
    half2* op = (half2*)(out + row * EDIM + t * 4);
    op[0] = h0; op[1] = h1;
}

// ---------------------------------------------------------------------------
// Flash attention fp16, non-causal. CTA = 256 q-rows of one (b,h), 8 warps.
// Q fragments hoisted to registers (reused across all 16 KV tiles);
// K/P via ldmatrix, V via ldmatrix.trans. Double-buffered K/V cp.async.
// ---------------------------------------------------------------------------
#define QSTR 72   // halves per row (64 + 8 pad)
#define FL_QOFF 0
#define FL_KOFF (256 * QSTR)
#define FL_VOFF (FL_KOFF + 2 * 64 * QSTR)
#define FL_POFF (FL_VOFF + 2 * 64 * QSTR)
#define FL_SMEM_H (FL_POFF + 256 * QSTR)

__global__ void __launch_bounds__(256)
flash_kernel(const __half* __restrict__ qkv, __half* __restrict__ ycat) {
    extern __shared__ __half sh[];
    __half* Qsm = sh + FL_QOFF;
    __half* Psm = sh + FL_POFF;

    const int tid  = threadIdx.x;
    const int lane = tid & 31;
    const int warp = tid >> 5;
    const int lr = lane >> 2;
    const int lc = lane & 3;
    const int q0 = blockIdx.x * 256;
    const int h  = blockIdx.y;
    const int b  = blockIdx.z;
    const int wm = warp * 32;

    const __half* qkvb = qkv + (long long)b * TSEQ * 3 * EDIM;
    const __half* Qg = qkvb + h * HD;
    const __half* Kg = qkvb + EDIM + h * HD;
    const __half* Vg = qkvb + 2 * EDIM + h * HD;

    // Q tile into smem (scaled by 0.125 — exact exponent shift)
    const half2 qsc = __floats2half2_rn(0.125f, 0.125f);
    #pragma unroll
    for (int i = tid; i < 256 * 8; i += 256) {
        int r = i >> 3, ch = (i & 7) << 3;
        uint4 v = *(const uint4*)(Qg + (long long)(q0 + r) * 3 * EDIM + ch);
        half2* hv = (half2*)&v;
        hv[0] = __hmul2(hv[0], qsc); hv[1] = __hmul2(hv[1], qsc);
        hv[2] = __hmul2(hv[2], qsc); hv[3] = __hmul2(hv[3], qsc);
        *(uint4*)(Qsm + r * QSTR + ch) = v;
    }

    auto load_kv = [&](int j, int buf) {
        __half* Ks = sh + FL_KOFF + buf * 64 * QSTR;
        __half* Vs = sh + FL_VOFF + buf * 64 * QSTR;
        const __half* Kj = Kg + (long long)(j * 64) * 3 * EDIM;
        const __half* Vj = Vg + (long long)(j * 64) * 3 * EDIM;
        #pragma unroll
        for (int i = tid; i < 64 * 8; i += 256) {
            int r = i >> 3, ch = (i & 7) << 3;
            cp_async16(Ks + r * QSTR + ch, Kj + (long long)r * 3 * EDIM + ch);
            cp_async16(Vs + r * QSTR + ch, Vj + (long long)r * 3 * EDIM + ch);
        }
        cp_commit();
    };

    load_kv(0, 0);
    __syncthreads();   // Q smem ready for fragment hoist

    // Hoist Q fragments: qfr[kstep][im][4], reused for all KV tiles.
    uint32_t qfr[4][2][4];
    #pragma unroll
    for (int ks = 0; ks < 4; ks++) {
        #pragma unroll
        for (int im = 0; im < 2; im++) {
            uint32_t sa = (uint32_t)__cvta_generic_to_shared(
                Qsm + (wm + im * 16 + (lane & 15)) * QSTR + ks * 16 + ((lane >> 4) << 3));
            ldmatrix_x4(qfr[ks][im][0], qfr[ks][im][1], qfr[ks][im][2], qfr[ks][im][3], sa);
        }
    }

    float o[2][8][4];
    float m[2][2], l[2][2];
    #pragma unroll
    for (int im = 0; im < 2; im++) {
        #pragma unroll
        for (int jn = 0; jn < 8; jn++)
            #pragma unroll
            for (int q = 0; q < 4; q++) o[im][jn][q] = 0.0f;
        m[im][0] = m[im][1] = -1e30f;
        l[im][0] = l[im][1] = 0.0f;
    }

    const int NT = TSEQ / 64;
    for (int j = 0; j < NT; j++) {
        const int buf = j & 1;
        if (j + 1 < NT) { load_kv(j + 1, buf ^ 1); cp_wait<1>(); }
        else           { cp_wait<0>(); }
        __syncthreads();

        const __half* Ks = sh + FL_KOFF + buf * 64 * QSTR;
        const __half* Vs = sh + FL_VOFF + buf * 64 * QSTR;

        // ---- S = Q K^T ----
        float s[2][8][4];
        #pragma unroll
        for (int im = 0; im < 2; im++)
            #pragma unroll
            for (int jn = 0; jn < 8; jn++)
                #pragma unroll
                for (int q = 0; q < 4; q++) s[im][jn][q] = 0.0f;

        #pragma unroll
        for (int ks = 0; ks < 4; ks++) {
            #pragma unroll
            for (int jn = 0; jn < 8; jn++) {
                uint32_t bfr[2];
                uint32_t sb = (uint32_t)__cvta_generic_to_shared(
                    Ks + (jn * 8 + (lane & 7)) * QSTR + ks * 16 + (((lane >> 3) & 3) == 1 ? 8 : 0));
                ldmatrix_x2(bfr[0], bfr[1], sb);
                #pragma unroll
                for (int im = 0; im < 2; im++) mma_f16(s[im][jn], qfr[ks][im], bfr);
            }
        }

        // ---- online softmax; write fp16 P (own rows) ----
        #pragma unroll
        for (int im = 0; im < 2; im++) {
            #pragma unroll
            for (int hf = 0; hf < 2; hf++) {
                float mx = -1e30f;
                #pragma unroll
                for (int jn = 0; jn < 8; jn++)
                    mx = fmaxf(mx, fmaxf(s[im][jn][hf * 2], s[im][jn][hf * 2 + 1]));
                mx = fmaxf(mx, __shfl_xor_sync(~0u, mx, 1));
                mx = fmaxf(mx, __shfl_xor_sync(~0u, mx, 2));
                const float mnew = fmaxf(m[im][hf], mx);
                const float alpha = __expf(m[im][hf] - mnew);
                m[im][hf] = mnew;
                const int prow = wm + im * 16 + hf * 8 + lr;
                float sum = 0.0f;
                #pragma unroll
                for (int jn = 0; jn < 8; jn++) {
                    float p0 = __expf(s[im][jn][hf * 2]     - mnew);
                    float p1 = __expf(s[im][jn][hf * 2 + 1] - mnew);
                    sum += p0 + p1;
                    *(half2*)(Psm + prow * QSTR + jn * 8 + 2 * lc) = __floats2half2_rn(p0, p1);
                }
                sum += __shfl_xor_sync(~0u, sum, 1);
                sum += __shfl_xor_sync(~0u, sum, 2);
                l[im][hf] = l[im][hf] * alpha + sum;
                #pragma unroll
                for (int jn = 0; jn < 8; jn++) {
                    o[im][jn][hf * 2]     *= alpha;
                    o[im][jn][hf * 2 + 1] *= alpha;
                }
            }
        }
        __syncwarp();

        // ---- O += P @ V ----
        #pragma unroll
        for (int ks = 0; ks < 4; ks++) {
            uint32_t afr[2][4];
            #pragma unroll
            for (int im = 0; im < 2; im++) {
                uint32_t sa = (uint32_t)__cvta_generic_to_shared(
                    Psm + (wm + im * 16 + (lane & 15)) * QSTR + ks * 16 + ((lane >> 4) << 3));
                ldmatrix_x4(afr[im][0], afr[im][1], afr[im][2], afr[im][3], sa);
            }
            #pragma unroll
            for (int jn = 0; jn < 8; jn++) {
                uint32_t bfr[2];
                uint32_t sv = (uint32_t)__cvta_generic_to_shared(
                    Vs + (ks * 16 + (lane & 15)) * QSTR + jn * 8);
                ldmatrix_x2_trans(bfr[0], bfr[1], sv);
                #pragma unroll
                for (int im = 0; im < 2; im++) mma_f16(o[im][jn], afr[im], bfr);
            }
        }
        __syncthreads();
    }

    // ycat (fp16; feeds Wproj GEMM)
    #pragma unroll
    for (int im = 0; im < 2; im++) {
        #pragma unroll
        for (int hf = 0; hf < 2; hf++) {
            const float inv = 1.0f / l[im][hf];
            const long long row = (long long)b * TSEQ + q0 + wm + im * 16 + hf * 8 + lr;
            #pragma unroll
            for (int jn = 0; jn < 8; jn++) {
                *(half2*)(ycat + row * EDIM + h * HD + jn * 8 + 2 * lc) =
                    __floats2half2_rn(o[im][jn][hf * 2] * inv, o[im][jn][hf * 2 + 1] * inv);
            }
        }
    }
}

// ---------------------------------------------------------------------------
// fp16 GEMM: 128x128x32 CTA tile, 8 warps x (64x32), 3-stage cp.async,
// __launch_bounds__(256,2). ldmatrix fragment loads.
// EPI: 1 +bias, 2 +bias,GELU, 3 +bias,+res(fp32). HOUT: fp16 C, else fp32.
// ---------------------------------------------------------------------------
#define GBM 128
#define GBN 128
#define GBK 32
#define GSTR 40               // halves per smem row (32 + 8 pad)
#define TILE_H (128 * GSTR)
#define G_SMEM_B (3 * 2 * TILE_H * 2)

template <int EPI, bool HOUT>
__global__ void __launch_bounds__(256, 2)
mma_gemm(int K,
         const __half* __restrict__ A, int lda,
         const __half* __restrict__ BT, int ldb,
         void* __restrict__ Cv, int ldc,
         const float* __restrict__ bias,
         const float* __restrict__ res) {
    extern __shared__ __half gsh[];
    const int m0 = blockIdx.y * GBM;
    const int n0 = blockIdx.x * GBN;
    const int tid  = threadIdx.x;
    const int lane = tid & 31;
    const int warp = tid >> 5;
    const int wm = (warp >> 2) * 64;     // 2 m-warps
    const int wn = (warp & 3) * 32;      // 4 n-warps
    const int lr = lane >> 2;
    const int lc = lane & 3;

    float acc[4][4][4];
    #pragma unroll
    for (int i = 0; i < 4; i++)
        #pragma unroll
        for (int j = 0; j < 4; j++)
            #pragma unroll
            for (int q = 0; q < 4; q++) acc[i][j][q] = 0.0f;

    const int KT = K / GBK;

    auto load_tile = [&](int kt, int st) {
        __half* As = gsh + st * 2 * TILE_H;
        __half* Bs = gsh + st * 2 * TILE_H + TILE_H;
        const int k0 = kt * GBK;
        #pragma unroll
        for (int i = tid; i < 512; i += 256) {
            int r = i >> 2, ch = (i & 3) << 3;
            cp_async16(As + r * GSTR + ch, A  + (long long)(m0 + r) * lda + k0 + ch);
        }
        #pragma unroll
        for (int i = tid; i < 512; i += 256) {
            int r = i >> 2, ch = (i & 3) << 3;
            cp_async16(Bs + r * GSTR + ch, BT + (long long)(n0 + r) * ldb + k0 + ch);
        }
        cp_commit();
    };

    load_tile(0, 0);
    load_tile(1, 1);

    int st = 0;
    for (int kt = 0; kt < KT; kt++) {
        cp_wait<1>();
        __syncthreads();
        if (kt + 2 < KT) {
            int st2 = st + 2; if (st2 >= 3) st2 -= 3;
            load_tile(kt + 2, st2);
        }
        const __half* As = gsh + st * 2 * TILE_H;
        const __half* Bs = gsh + st * 2 * TILE_H + TILE_H;

        #pragma unroll
        for (int kq = 0; kq < GBK; kq += 16) {
            uint32_t afr[4][4];
            #pragma unroll
            for (int im = 0; im < 4; im++) {
                uint32_t sa = (uint32_t)__cvta_generic_to_shared(
                    As + (wm + im * 16 + (lane & 15)) * GSTR + kq + ((lane >> 4) << 3));
                ldmatrix_x4(afr[im][0], afr[im][1], afr[im][2], afr[im][3], sa);
            }
            #pragma unroll
            for (int jn = 0; jn < 4; jn++) {
                uint32_t bfr[2];
                uint32_t sb = (uint32_t)__cvta_generic_to_shared(
                    Bs + (wn + jn * 8 + (lane & 7)) * GSTR + kq + (((lane >> 3) & 1) << 3));
                ldmatrix_x2(bfr[0], bfr[1], sb);
                #pragma unroll
                for (int im = 0; im < 4; im++) mma_f16(acc[im][jn], afr[im], bfr);
            }
        }
        __syncthreads();
        if (++st == 3) st = 0;
    }

    #pragma unroll
    for (int im = 0; im < 4; im++) {
        const int r0 = m0 + wm + im * 16 + lr;
        #pragma unroll
        for (int jn = 0; jn < 4; jn++) {
            const int cb = n0 + wn + jn * 8 + lc * 2;
            float bv0 = bias[cb], bv1 = bias[cb + 1];
            #pragma unroll
            for (int hf = 0; hf < 2; hf++) {
                const int r = r0 + hf * 8;
                float v0 = acc[im][jn][hf * 2]     + bv0;
                float v1 = acc[im][jn][hf * 2 + 1] + bv1;
                if (EPI == 2) { v0 = gelu_tanh(v0); v1 = gelu_tanh(v1); }
                if (EPI == 3) {
                    const float* rp = res + (long long)r * ldc + cb;
                    v0 += rp[0]; v1 += rp[1];
                }
                if (HOUT) {
                    *(half2*)((__half*)Cv + (long long)r * ldc + cb) =
                        __floats2half2_rn(v0, v1);
                } else {
                    float* cp = (float*)Cv + (long long)r * ldc + cb;
                    cp[0] = v0; cp[1] = v1;
                }
            }
        }
    }
}

// ---------------------------------------------------------------------------
extern "C" void kernel_launch(void* const* d_in, const int* in_sizes, int n_in,
                              void* d_out, int out_size) {
    const float* x     = (const float*)d_in[0];
    const float* ln1g  = (const float*)d_in[1];
    const float* ln1b  = (const float*)d_in[2];
    const float* Wqkv  = (const float*)d_in[3];
    const float* bqkv  = (const float*)d_in[4];
    const float* Wproj = (const float*)d_in[5];
    const float* bproj = (const float*)d_in[6];
    const float* ln2g  = (const float*)d_in[7];
    const float* ln2b  = (const float*)d_in[8];
    const float* Wfc   = (const float*)d_in[9];
    const float* bfc   = (const float*)d_in[10];
    const float* Wout  = (const float*)d_in[11];
    const float* bout  = (const float*)d_in[12];
    float* out = (float*)d_out;

    __half *xn, *qkv, *ycat, *hbuf, *wh;
    cudaGetSymbolAddress((void**)&xn,   g_xn);
    cudaGetSymbolAddress((void**)&qkv,  g_qkv);
    cudaGetSymbolAddress((void**)&ycat, g_ycat);
    cudaGetSymbolAddress((void**)&hbuf, g_h);
    cudaGetSymbolAddress((void**)&wh,   g_wh);

    const int gsmem = G_SMEM_B;                    // 61440 B
    const int fsmem = FL_SMEM_H * sizeof(__half);  // 110592 B
    static bool attr_done = false;
    if (!attr_done) {
        cudaFuncSetAttribute(mma_gemm<1,true >, cudaFuncAttributeMaxDynamicSharedMemorySize, gsmem);
        cudaFuncSetAttribute(mma_gemm<2,true >, cudaFuncAttributeMaxDynamicSharedMemorySize, gsmem);
        cudaFuncSetAttribute(mma_gemm<3,false>, cudaFuncAttributeMaxDynamicSharedMemorySize, gsmem);
        cudaFuncSetAttribute(flash_kernel, cudaFuncAttributeMaxDynamicSharedMemorySize, fsmem);
        attr_done = true;
    }

    // 0) transpose + fp16-convert weights: WT[n][k]
    transpose_half<<<dim3(3 * EDIM / 32, EDIM / 32), dim3(32, 8)>>>(Wqkv,  wh + WR_QKV,  EDIM, 3 * EDIM);
    transpose_half<<<dim3(EDIM / 32,     EDIM / 32), dim3(32, 8)>>>(Wproj, wh + WR_PROJ, EDIM, EDIM);
    transpose_half<<<dim3(HID / 32,      EDIM / 32), dim3(32, 8)>>>(Wfc,   wh + WR_FC,   EDIM, HID);
    transpose_half<<<dim3(EDIM / 32,     HID / 32),  dim3(32, 8)>>>(Wout,  wh + WR_OUT,  HID,  EDIM);

    // 1) LN1 -> fp16
    ln_kernel<<<RROWS, 256>>>(x, ln1g, ln1b, xn);

    // 2) QKV = LN1(x) @ Wqkv + bqkv  (fp16 out; feeds flash)
    mma_gemm<1,true><<<dim3(3 * EDIM / GBN, RROWS / GBM), 256, gsmem>>>(
        EDIM, xn, EDIM, wh + WR_QKV, EDIM, qkv, 3 * EDIM, bqkv, nullptr);

    // 3) flash attention -> ycat (fp16)
    flash_kernel<<<dim3(TSEQ / 256, HEADS, BATCH), 256, fsmem>>>(qkv, ycat);

    // 4) x1 = x + ycat @ Wproj + bproj -> d_out (fp32)
    mma_gemm<3,false><<<dim3(EDIM / GBN, RROWS / GBM), 256, gsmem>>>(
        EDIM, ycat, EDIM, wh + WR_PROJ, EDIM, out, EDIM, bproj, x);

    // 5) LN2(x1) -> fp16
    ln_kernel<<<RROWS, 256>>>(out, ln2g, ln2b, xn);

    // 6) h = gelu(xn @ Wfc + bfc)  (fp16 out)
    mma_gemm<2,true><<<dim3(HID / GBN, RROWS / GBM), 256, gsmem>>>(
        EDIM, xn, EDIM, wh + WR_FC, EDIM, hbuf, HID, bfc, nullptr);

    // 7) out = x1 + h @ Wout + bout (fp32)
    mma_gemm<3,false><<<dim3(EDIM / GBN, RROWS / GBM), 256, gsmem>>>(
        HID, hbuf, HID, wh + WR_OUT, HID, out, EDIM, bout, out);
}

// round 14
// speedup vs baseline: 3.0869x; 1.1329x over previous
#include <cuda_runtime.h>
#include <cuda_fp16.h>
#include <cstdint>

// ---------------------------------------------------------------------------
// TransformerBlock B=8,T=1024,E=1024,H=16,HD=64,HID=4096 fp32.
// R13b: fp16 m16n8k16 GEMM with GBK=64, 3-stage cp.async, software-pipelined
// fragments (A x4 / B x4 ldmatrix double-buffered across k-slices), correct
// tail cp_wait. Flash/LN/transpose unchanged from R13 (1003us).
// ---------------------------------------------------------------------------

#define RROWS 8192
#define EDIM  1024
#define HEADS 16
#define HD    64
#define HID   4096
#define TSEQ  1024
#define BATCH 8

__device__ __half g_xn  [RROWS * EDIM];
__device__ __half g_qkv [RROWS * 3 * EDIM];
__device__ __half g_ycat[RROWS * EDIM];
__device__ __half g_h   [RROWS * HID];
__device__ __half g_wh  [12582912];   // transposed fp16 weights

#define WR_QKV  0            // [3072][1024]
#define WR_PROJ 3145728      // [1024][1024]
#define WR_FC   4194304      // [4096][1024]
#define WR_OUT  8388608      // [1024][4096]

__device__ __forceinline__ float gelu_tanh(float x) {
    float x3 = x * x * x;
    return 0.5f * x * (1.0f + tanhf(0.7978845608028654f * (x + 0.044715f * x3)));
}
__device__ __forceinline__ void cp_async16(void* smem_dst, const void* gsrc) {
    uint32_t d = (uint32_t)__cvta_generic_to_shared(smem_dst);
    asm volatile("cp.async.cg.shared.global [%0], [%1], 16;\n" :: "r"(d), "l"(gsrc));
}
__device__ __forceinline__ void cp_commit() { asm volatile("cp.async.commit_group;\n"); }
template <int N>
__device__ __forceinline__ void cp_wait() { asm volatile("cp.async.wait_group %0;\n" :: "n"(N)); }

// m16n8k16 fp16 MMA, fp32 accumulate.
__device__ __forceinline__ void mma_f16(float* c, const uint32_t* a, const uint32_t* b) {
    asm volatile(
        "mma.sync.aligned.m16n8k16.row.col.f32.f16.f16.f32 "
        "{%0,%1,%2,%3}, {%4,%5,%6,%7}, {%8,%9}, {%0,%1,%2,%3};"
        : "+f"(c[0]), "+f"(c[1]), "+f"(c[2]), "+f"(c[3])
        : "r"(a[0]), "r"(a[1]), "r"(a[2]), "r"(a[3]), "r"(b[0]), "r"(b[1]));
}

__device__ __forceinline__ void ldmatrix_x4(uint32_t& r0, uint32_t& r1, uint32_t& r2,
                                            uint32_t& r3, uint32_t saddr) {
    asm volatile("ldmatrix.sync.aligned.m8n8.x4.shared.b16 {%0,%1,%2,%3}, [%4];"
                 : "=r"(r0), "=r"(r1), "=r"(r2), "=r"(r3) : "r"(saddr));
}
__device__ __forceinline__ void ldmatrix_x2(uint32_t& r0, uint32_t& r1, uint32_t saddr) {
    asm volatile("ldmatrix.sync.aligned.m8n8.x2.shared.b16 {%0,%1}, [%2];"
                 : "=r"(r0), "=r"(r1) : "r"(saddr));
}
__device__ __forceinline__ void ldmatrix_x2_trans(uint32_t& r0, uint32_t& r1, uint32_t saddr) {
    asm volatile("ldmatrix.sync.aligned.m8n8.x2.trans.shared.b16 {%0,%1}, [%2];"
                 : "=r"(r0), "=r"(r1) : "r"(saddr));
}

// ---------------------------------------------------------------------------
// Weight transpose + fp16 convert:  WT[n][k] = half(W[k][n]).  in: [K][N].
// ---------------------------------------------------------------------------
__global__ void transpose_half(const float* __restrict__ in, __half* __restrict__ outp,
                               int K, int N) {
    __shared__ float t[32][33];
    const int n0 = blockIdx.x * 32, k0 = blockIdx.y * 32;
    const int tx = threadIdx.x, ty = threadIdx.y;
    #pragma unroll
    for (int j = 0; j < 32; j += 8)
        t[ty + j][tx] = in[(long long)(k0 + ty + j) * N + n0 + tx];
    __syncthreads();
    #pragma unroll
    for (int j = 0; j < 32; j += 8)
        outp[(long long)(n0 + ty + j) * K + k0 + tx] = __float2half(t[tx][ty + j]);
}

// ---------------------------------------------------------------------------
// LayerNorm: one block (256 threads) per 1024-col row; fp32 in, fp16 out.
// ---------------------------------------------------------------------------
__global__ void ln_kernel(const float* __restrict__ x,
                          const float* __restrict__ g,
                          const float* __restrict__ b,
                          __half* __restrict__ out) {
    __shared__ float red[8];
    const long long row = blockIdx.x;
    const int t = threadIdx.x;
    float4 v = ((const float4*)(x + row * EDIM))[t];

    float s = v.x + v.y + v.z + v.w;
    #pragma unroll
    for (int o = 16; o; o >>= 1) s += __shfl_xor_sync(~0u, s, o);
    if ((t & 31) == 0) red[t >> 5] = s;
    __syncthreads();
    if (t < 8) {
        s = red[t];
        #pragma unroll
        for (int o = 4; o; o >>= 1) s += __shfl_xor_sync(0xffu, s, o);
        if (t == 0) red[0] = s;
    }
    __syncthreads();
    const float mean = red[0] * (1.0f / EDIM);

    float dx = v.x - mean, dy = v.y - mean, dz = v.z - mean, dw = v.w - mean;
    float q = dx * dx + dy * dy + dz * dz + dw * dw;
    #pragma unroll
    for (int o = 16; o; o >>= 1) q += __shfl_xor_sync(~0u, q, o);
    __syncthreads();
    if ((t & 31) == 0) red[t >> 5] = q;
    __syncthreads();
    if (t < 8) {
        q = red[t];
        #pragma unroll
        for (int o = 4; o; o >>= 1) q += __shfl_xor_sync(0xffu, q, o);
        if (t == 0) red[0] = q;
    }
    __syncthreads();
    const float rstd = rsqrtf(red[0] * (1.0f / EDIM) + 1e-5f);

    const float4 gg = ((const float4*)g)[t];
    const float4 bb = ((const float4*)b)[t];
    half2 h0 = __floats2half2_rn(dx * rstd * gg.x + bb.x, dy * rstd * gg.y + bb.y);
    half2 h1 = __floats2half2_rn(dz * rstd * gg.z + bb.z, dw * rstd * gg.w + bb.w);
    half2* op = (half2*)(out + row * EDIM + t * 4);
    op[0] = h0; op[1] = h1;
}

// ---------------------------------------------------------------------------
// Flash attention fp16, non-causal — unchanged from R13.
// ---------------------------------------------------------------------------
#define QSTR 72   // halves per row (64 + 8 pad)
#define FL_QOFF 0
#define FL_KOFF (256 * QSTR)
#define FL_VOFF (FL_KOFF + 2 * 64 * QSTR)
#define FL_POFF (FL_VOFF + 2 * 64 * QSTR)
#define FL_SMEM_H (FL_POFF + 256 * QSTR)

__global__ void __launch_bounds__(256)
flash_kernel(const __half* __restrict__ qkv, __half* __restrict__ ycat) {
    extern __shared__ __half sh[];
    __half* Qsm = sh + FL_QOFF;
    __half* Psm = sh + FL_POFF;

    const int tid  = threadIdx.x;
    const int lane = tid & 31;
    const int warp = tid >> 5;
    const int lr = lane >> 2;
    const int lc = lane & 3;
    const int q0 = blockIdx.x * 256;
    const int h  = blockIdx.y;
    const int b  = blockIdx.z;
    const int wm = warp * 32;

    const __half* qkvb = qkv + (long long)b * TSEQ * 3 * EDIM;
    const __half* Qg = qkvb + h * HD;
    const __half* Kg = qkvb + EDIM + h * HD;
    const __half* Vg = qkvb + 2 * EDIM + h * HD;

    const half2 qsc = __floats2half2_rn(0.125f, 0.125f);
    #pragma unroll
    for (int i = tid; i < 256 * 8; i += 256) {
        int r = i >> 3, ch = (i & 7) << 3;
        uint4 v = *(const uint4*)(Qg + (long long)(q0 + r) * 3 * EDIM + ch);
        half2* hv = (half2*)&v;
        hv[0] = __hmul2(hv[0], qsc); hv[1] = __hmul2(hv[1], qsc);
        hv[2] = __hmul2(hv[2], qsc); hv[3] = __hmul2(hv[3], qsc);
        *(uint4*)(Qsm + r * QSTR + ch) = v;
    }

    auto load_kv = [&](int j, int buf) {
        __half* Ks = sh + FL_KOFF + buf * 64 * QSTR;
        __half* Vs = sh + FL_VOFF + buf * 64 * QSTR;
        const __half* Kj = Kg + (long long)(j * 64) * 3 * EDIM;
        const __half* Vj = Vg + (long long)(j * 64) * 3 * EDIM;
        #pragma unroll
        for (int i = tid; i < 64 * 8; i += 256) {
            int r = i >> 3, ch = (i & 7) << 3;
            cp_async16(Ks + r * QSTR + ch, Kj + (long long)r * 3 * EDIM + ch);
            cp_async16(Vs + r * QSTR + ch, Vj + (long long)r * 3 * EDIM + ch);
        }
        cp_commit();
    };

    load_kv(0, 0);
    __syncthreads();

    uint32_t qfr[4][2][4];
    #pragma unroll
    for (int ks = 0; ks < 4; ks++) {
        #pragma unroll
        for (int im = 0; im < 2; im++) {
            uint32_t sa = (uint32_t)__cvta_generic_to_shared(
                Qsm + (wm + im * 16 + (lane & 15)) * QSTR + ks * 16 + ((lane >> 4) << 3));
            ldmatrix_x4(qfr[ks][im][0], qfr[ks][im][1], qfr[ks][im][2], qfr[ks][im][3], sa);
        }
    }

    float o[2][8][4];
    float m[2][2], l[2][2];
    #pragma unroll
    for (int im = 0; im < 2; im++) {
        #pragma unroll
        for (int jn = 0; jn < 8; jn++)
            #pragma unroll
            for (int q = 0; q < 4; q++) o[im][jn][q] = 0.0f;
        m[im][0] = m[im][1] = -1e30f;
        l[im][0] = l[im][1] = 0.0f;
    }

    const int NT = TSEQ / 64;
    for (int j = 0; j < NT; j++) {
        const int buf = j & 1;
        if (j + 1 < NT) { load_kv(j + 1, buf ^ 1); cp_wait<1>(); }
        else           { cp_wait<0>(); }
        __syncthreads();

        const __half* Ks = sh + FL_KOFF + buf * 64 * QSTR;
        const __half* Vs = sh + FL_VOFF + buf * 64 * QSTR;

        float s[2][8][4];
        #pragma unroll
        for (int im = 0; im < 2; im++)
            #pragma unroll
            for (int jn = 0; jn < 8; jn++)
                #pragma unroll
                for (int q = 0; q < 4; q++) s[im][jn][q] = 0.0f;

        #pragma unroll
        for (int ks = 0; ks < 4; ks++) {
            #pragma unroll
            for (int jn = 0; jn < 8; jn++) {
                uint32_t bfr[2];
                uint32_t sb = (uint32_t)__cvta_generic_to_shared(
                    Ks + (jn * 8 + (lane & 7)) * QSTR + ks * 16 + (((lane >> 3) & 3) == 1 ? 8 : 0));
                ldmatrix_x2(bfr[0], bfr[1], sb);
                #pragma unroll
                for (int im = 0; im < 2; im++) mma_f16(s[im][jn], qfr[ks][im], bfr);
            }
        }

        #pragma unroll
        for (int im = 0; im < 2; im++) {
            #pragma unroll
            for (int hf = 0; hf < 2; hf++) {
                float mx = -1e30f;
                #pragma unroll
                for (int jn = 0; jn < 8; jn++)
                    mx = fmaxf(mx, fmaxf(s[im][jn][hf * 2], s[im][jn][hf * 2 + 1]));
                mx = fmaxf(mx, __shfl_xor_sync(~0u, mx, 1));
                mx = fmaxf(mx, __shfl_xor_sync(~0u, mx, 2));
                const float mnew = fmaxf(m[im][hf], mx);
                const float alpha = __expf(m[im][hf] - mnew);
                m[im][hf] = mnew;
                const int prow = wm + im * 16 + hf * 8 + lr;
                float sum = 0.0f;
                #pragma unroll
                for (int jn = 0; jn < 8; jn++) {
                    float p0 = __expf(s[im][jn][hf * 2]     - mnew);
                    float p1 = __expf(s[im][jn][hf * 2 + 1] - mnew);
                    sum += p0 + p1;
                    *(half2*)(Psm + prow * QSTR + jn * 8 + 2 * lc) = __floats2half2_rn(p0, p1);
                }
                sum += __shfl_xor_sync(~0u, sum, 1);
                sum += __shfl_xor_sync(~0u, sum, 2);
                l[im][hf] = l[im][hf] * alpha + sum;
                #pragma unroll
                for (int jn = 0; jn < 8; jn++) {
                    o[im][jn][hf * 2]     *= alpha;
                    o[im][jn][hf * 2 + 1] *= alpha;
                }
            }
        }
        __syncwarp();

        #pragma unroll
        for (int ks = 0; ks < 4; ks++) {
            uint32_t afr[2][4];
            #pragma unroll
            for (int im = 0; im < 2; im++) {
                uint32_t sa = (uint32_t)__cvta_generic_to_shared(
                    Psm + (wm + im * 16 + (lane & 15)) * QSTR + ks * 16 + ((lane >> 4) << 3));
                ldmatrix_x4(afr[im][0], afr[im][1], afr[im][2], afr[im][3], sa);
            }
            #pragma unroll
            for (int jn = 0; jn < 8; jn++) {
                uint32_t bfr[2];
                uint32_t sv = (uint32_t)__cvta_generic_to_shared(
                    Vs + (ks * 16 + (lane & 15)) * QSTR + jn * 8);
                ldmatrix_x2_trans(bfr[0], bfr[1], sv);
                #pragma unroll
                for (int im = 0; im < 2; im++) mma_f16(o[im][jn], afr[im], bfr);
            }
        }
        __syncthreads();
    }

    #pragma unroll
    for (int im = 0; im < 2; im++) {
        #pragma unroll
        for (int hf = 0; hf < 2; hf++) {
            const float inv = 1.0f / l[im][hf];
            const long long row = (long long)b * TSEQ + q0 + wm + im * 16 + hf * 8 + lr;
            #pragma unroll
            for (int jn = 0; jn < 8; jn++) {
                *(half2*)(ycat + row * EDIM + h * HD + jn * 8 + 2 * lc) =
                    __floats2half2_rn(o[im][jn][hf * 2] * inv, o[im][jn][hf * 2 + 1] * inv);
            }
        }
    }
}

// ---------------------------------------------------------------------------
// fp16 GEMM: 128x128x64 CTA tile, 8 warps x (64x32), 3-stage cp.async,
// software-pipelined fragments (A x4 / B x4 ldmatrix, double-buffered
// across the 4 k-slices of each stage). 110.6KB smem -> 1 CTA/SM, 8 warps.
// EPI: 1 +bias, 2 +bias,GELU, 3 +bias,+res(fp32). HOUT: fp16 C, else fp32.
// ---------------------------------------------------------------------------
#define GBM 128
#define GBN 128
#define GBK 64
#define GSTR 72               // halves per smem row (64 + 8 pad; 144B = 9x16B)
#define TILE_H (128 * GSTR)
#define G_SMEM_B (3 * 2 * TILE_H * 2)

template <int EPI, bool HOUT>
__global__ void __launch_bounds__(256)
mma_gemm(int K,
         const __half* __restrict__ A, int lda,
         const __half* __restrict__ BT, int ldb,
         void* __restrict__ Cv, int ldc,
         const float* __restrict__ bias,
         const float* __restrict__ res) {
    extern __shared__ __half gsh[];
    const int m0 = blockIdx.y * GBM;
    const int n0 = blockIdx.x * GBN;
    const int tid  = threadIdx.x;
    const int lane = tid & 31;
    const int warp = tid >> 5;
    const int wm = (warp >> 2) * 64;     // 2 m-warps
    const int wn = (warp & 3) * 32;      // 4 n-warps
    const int lr = lane >> 2;
    const int lc = lane & 3;

    float acc[4][4][4];
    #pragma unroll
    for (int i = 0; i < 4; i++)
        #pragma unroll
        for (int j = 0; j < 4; j++)
            #pragma unroll
            for (int q = 0; q < 4; q++) acc[i][j][q] = 0.0f;

    const int KT = K / GBK;

    auto load_tile = [&](int kt, int st) {
        __half* As = gsh + st * 2 * TILE_H;
        __half* Bs = gsh + st * 2 * TILE_H + TILE_H;
        const int k0 = kt * GBK;
        // 128 rows x 64 halves = 8 chunks of 16B per row, each operand
        #pragma unroll
        for (int i = tid; i < 1024; i += 256) {
            int r = i >> 3, ch = (i & 7) << 3;
            cp_async16(As + r * GSTR + ch, A  + (long long)(m0 + r) * lda + k0 + ch);
        }
        #pragma unroll
        for (int i = tid; i < 1024; i += 256) {
            int r = i >> 3, ch = (i & 7) << 3;
            cp_async16(Bs + r * GSTR + ch, BT + (long long)(n0 + r) * ldb + k0 + ch);
        }
        cp_commit();
    };

    // Fragment loaders (double-buffered across k-slices).
    uint32_t afr[2][4][4];   // [buf][im][regs]
    uint32_t bfr[2][2][4];   // [buf][pair][regs]: pair p covers jn=2p,2p+1

    auto ld_frag = [&](const __half* As, const __half* Bs, int ks, int buf) {
        const int kq = ks * 16;
        #pragma unroll
        for (int im = 0; im < 4; im++) {
            uint32_t sa = (uint32_t)__cvta_generic_to_shared(
                As + (wm + im * 16 + (lane & 15)) * GSTR + kq + ((lane >> 4) << 3));
            ldmatrix_x4(afr[buf][im][0], afr[buf][im][1], afr[buf][im][2], afr[buf][im][3], sa);
        }
        #pragma unroll
        for (int p = 0; p < 2; p++) {
            uint32_t sb = (uint32_t)__cvta_generic_to_shared(
                Bs + (wn + p * 16 + (lane & 7) + ((lane >> 4) << 3)) * GSTR
                   + kq + (((lane >> 3) & 1) << 3));
            ldmatrix_x4(bfr[buf][p][0], bfr[buf][p][1], bfr[buf][p][2], bfr[buf][p][3], sb);
        }
    };

    load_tile(0, 0);
    load_tile(1, 1);

    int st = 0;
    for (int kt = 0; kt < KT; kt++) {
        if (kt + 1 < KT) cp_wait<1>(); else cp_wait<0>();
        __syncthreads();
        if (kt + 2 < KT) {
            int st2 = st + 2; if (st2 >= 3) st2 -= 3;
            load_tile(kt + 2, st2);
        }
        const __half* As = gsh + st * 2 * TILE_H;
        const __half* Bs = gsh + st * 2 * TILE_H + TILE_H;

        ld_frag(As, Bs, 0, 0);
        #pragma unroll
        for (int ks = 0; ks < 4; ks++) {
            const int cur = ks & 1;
            if (ks < 3) ld_frag(As, Bs, ks + 1, cur ^ 1);
            #pragma unroll
            for (int p = 0; p < 2; p++)
                #pragma unroll
                for (int im = 0; im < 4; im++) {
                    mma_f16(acc[im][2 * p],     afr[cur][im], &bfr[cur][p][0]);
                    mma_f16(acc[im][2 * p + 1], afr[cur][im], &bfr[cur][p][2]);
                }
        }
        __syncthreads();
        if (++st == 3) st = 0;
    }

    #pragma unroll
    for (int im = 0; im < 4; im++) {
        const int r0 = m0 + wm + im * 16 + lr;
        #pragma unroll
        for (int jn = 0; jn < 4; jn++) {
            const int cb = n0 + wn + jn * 8 + lc * 2;
            float bv0 = bias[cb], bv1 = bias[cb + 1];
            #pragma unroll
            for (int hf = 0; hf < 2; hf++) {
                const int r = r0 + hf * 8;
                float v0 = acc[im][jn][hf * 2]     + bv0;
                float v1 = acc[im][jn][hf * 2 + 1] + bv1;
                if (EPI == 2) { v0 = gelu_tanh(v0); v1 = gelu_tanh(v1); }
                if (EPI == 3) {
                    const float* rp = res + (long long)r * ldc + cb;
                    v0 += rp[0]; v1 += rp[1];
                }
                if (HOUT) {
                    *(half2*)((__half*)Cv + (long long)r * ldc + cb) =
                        __floats2half2_rn(v0, v1);
                } else {
                    float* cp = (float*)Cv + (long long)r * ldc + cb;
                    cp[0] = v0; cp[1] = v1;
                }
            }
        }
    }
}

// ---------------------------------------------------------------------------
extern "C" void kernel_launch(void* const* d_in, const int* in_sizes, int n_in,
                              void* d_out, int out_size) {
    const float* x     = (const float*)d_in[0];
    const float* ln1g  = (const float*)d_in[1];
    const float* ln1b  = (const float*)d_in[2];
    const float* Wqkv  = (const float*)d_in[3];
    const float* bqkv  = (const float*)d_in[4];
    const float* Wproj = (const float*)d_in[5];
    const float* bproj = (const float*)d_in[6];
    const float* ln2g  = (const float*)d_in[7];
    const float* ln2b  = (const float*)d_in[8];
    const float* Wfc   = (const float*)d_in[9];
    const float* bfc   = (const float*)d_in[10];
    const float* Wout  = (const float*)d_in[11];
    const float* bout  = (const float*)d_in[12];
    float* out = (float*)d_out;

    __half *xn, *qkv, *ycat, *hbuf, *wh;
    cudaGetSymbolAddress((void**)&xn,   g_xn);
    cudaGetSymbolAddress((void**)&qkv,  g_qkv);
    cudaGetSymbolAddress((void**)&ycat, g_ycat);
    cudaGetSymbolAddress((void**)&hbuf, g_h);
    cudaGetSymbolAddress((void**)&wh,   g_wh);

    const int gsmem = G_SMEM_B;                    // 110592 B
    const int fsmem = FL_SMEM_H * sizeof(__half);  // 110592 B
    static bool attr_done = false;
    if (!attr_done) {
        cudaFuncSetAttribute(mma_gemm<1,true >, cudaFuncAttributeMaxDynamicSharedMemorySize, gsmem);
        cudaFuncSetAttribute(mma_gemm<2,true >, cudaFuncAttributeMaxDynamicSharedMemorySize, gsmem);
        cudaFuncSetAttribute(mma_gemm<3,false>, cudaFuncAttributeMaxDynamicSharedMemorySize, gsmem);
        cudaFuncSetAttribute(flash_kernel, cudaFuncAttributeMaxDynamicSharedMemorySize, fsmem);
        attr_done = true;
    }

    // 0) transpose + fp16-convert weights: WT[n][k]
    transpose_half<<<dim3(3 * EDIM / 32, EDIM / 32), dim3(32, 8)>>>(Wqkv,  wh + WR_QKV,  EDIM, 3 * EDIM);
    transpose_half<<<dim3(EDIM / 32,     EDIM / 32), dim3(32, 8)>>>(Wproj, wh + WR_PROJ, EDIM, EDIM);
    transpose_half<<<dim3(HID / 32,      EDIM / 32), dim3(32, 8)>>>(Wfc,   wh + WR_FC,   EDIM, HID);
    transpose_half<<<dim3(EDIM / 32,     HID / 32),  dim3(32, 8)>>>(Wout,  wh + WR_OUT,  HID,  EDIM);

    // 1) LN1 -> fp16
    ln_kernel<<<RROWS, 256>>>(x, ln1g, ln1b, xn);

    // 2) QKV = LN1(x) @ Wqkv + bqkv  (fp16 out; feeds flash)
    mma_gemm<1,true><<<dim3(3 * EDIM / GBN, RROWS / GBM), 256, gsmem>>>(
        EDIM, xn, EDIM, wh + WR_QKV, EDIM, qkv, 3 * EDIM, bqkv, nullptr);

    // 3) flash attention -> ycat (fp16)
    flash_kernel<<<dim3(TSEQ / 256, HEADS, BATCH), 256, fsmem>>>(qkv, ycat);

    // 4) x1 = x + ycat @ Wproj + bproj -> d_out (fp32)
    mma_gemm<3,false><<<dim3(EDIM / GBN, RROWS / GBM), 256, gsmem>>>(
        EDIM, ycat, EDIM, wh + WR_PROJ, EDIM, out, EDIM, bproj, x);

    // 5) LN2(x1) -> fp16
    ln_kernel<<<RROWS, 256>>>(out, ln2g, ln2b, xn);

    // 6) h = gelu(xn @ Wfc + bfc)  (fp16 out)
    mma_gemm<2,true><<<dim3(HID / GBN, RROWS / GBM), 256, gsmem>>>(
        EDIM, xn, EDIM, wh + WR_FC, EDIM, hbuf, HID, bfc, nullptr);

    // 7) out = x1 + h @ Wout + bout (fp32)
    mma_gemm<3,false><<<dim3(EDIM / GBN, RROWS / GBM), 256, gsmem>>>(
        HID, hbuf, HID, wh + WR_OUT, HID, out, EDIM, bout, out);
}